// round 11
// baseline (speedup 1.0000x reference)
#include <cuda_runtime.h>
#include <cuda_fp16.h>
#include <cstdint>

// ---------------- problem constants ----------------
#define NB      32
#define DIM     64
#define HW      1024
#define KCODES  2048
#define TOK_TILE 64
#define NBLOCKS  512          // TOKENS / TOK_TILE
#define NTILES   16           // KCODES / 128
#define BMARG    0.35f        // conservative |d2' - d_hi| bound (rigorous ~0.14)
#define WLIST    512          // per-warp candidate capacity

// ---------------- dynamic smem layout (bytes) ----------------
#define A_STRIDE 68
#define A_OFF    0u                       // fp32 A [64][68]  (17408 B)
#define B_OFF    17408u                   // 2 buffers x 16KB packed hi tiles
#define B_BUF    16384u
#define CN_OFF   50176u                   // 2 x 128 floats
#define DW_OFF   51200u                   // 192 floats
#define DB_OFF   51968u                   // 4 floats
#define CNT_OFF  51984u                   // 8 u32 per-warp counters (+pad)
#define LIST_OFF 52032u                   // 8 x WLIST u32
#define TOKMIN_OFF 68416u                 // 64 u64
#define RED_OFF  68928u                   // 512 floats
#define SMEM_TOTAL 71040u

__device__ float g_cnorm[KCODES];
__device__ float g_partial[2 * NBLOCKS];
__device__ unsigned int g_done = 0;
// packed fp16 HI codebook: per tile 4096 u32
// addr(u32) = nt*256 + lane*8 + kk*2 + r   (r: b0/b1 regs of m16n8k16 B frag)
__device__ uint32_t g_cbf[NTILES * 4096];

// ---------------- helpers ----------------
__device__ __forceinline__ uint32_t smem_u32(const void* p) {
    uint32_t a;
    asm("{ .reg .u64 t; cvta.to.shared.u64 t, %1; cvt.u32.u64 %0, t; }" : "=r"(a) : "l"(p));
    return a;
}
__device__ __forceinline__ uint32_t packh2(float x, float y) {
    __half2 h = __floats2half2_rn(x, y);
    return *reinterpret_cast<uint32_t*>(&h);
}
__device__ __forceinline__ void mma_f16(float* d, const uint32_t* a,
                                        uint32_t b0, uint32_t b1) {
    asm volatile(
        "mma.sync.aligned.m16n8k16.row.col.f32.f16.f16.f32 "
        "{%0,%1,%2,%3}, {%4,%5,%6,%7}, {%8,%9}, {%0,%1,%2,%3};"
        : "+f"(d[0]), "+f"(d[1]), "+f"(d[2]), "+f"(d[3])
        : "r"(a[0]), "r"(a[1]), "r"(a[2]), "r"(a[3]), "r"(b0), "r"(b1));
}
__device__ __forceinline__ void cp16(uint32_t s, const void* g) {
    asm volatile("cp.async.cg.shared.global [%0], [%1], 16;" :: "r"(s), "l"(g));
}
__device__ __forceinline__ void cp_commit() {
    asm volatile("cp.async.commit_group;" ::: "memory");
}
__device__ __forceinline__ void cp_wait0() {
    asm volatile("cp.async.wait_group 0;" ::: "memory");
}
__device__ __forceinline__ uint32_t fkey(float v) {
    uint32_t b = __float_as_uint(v);
    return (b & 0x80000000u) ? ~b : (b | 0x80000000u);
}

// ---------------- prep: codebook norms + packed fp16 hi tiles ----------------
// grid 128: blk = tile*8 + sub. sub packs nt = sub*2 + {0,1}; 16 cnorm rows.
__global__ void __launch_bounds__(256) vq_prep(const float* __restrict__ cb) {
    int blk = blockIdx.x;
    int tile = blk >> 3;
    int sub = blk & 7;
    int tid = threadIdx.x;
    int lane = tid & 31;
    int grp  = tid >> 5;                  // 0..7

    if (tid < 16) {
        int k = tile * 128 + sub * 16 + tid;
        const float* r = cb + (size_t)k * DIM;
        float s = 0.f;
#pragma unroll
        for (int c4 = 0; c4 < DIM / 4; ++c4) {
            float4 v = *(const float4*)(r + c4 * 4);
            s += v.x * v.x + v.y * v.y + v.z * v.z + v.w * v.w;
        }
        g_cnorm[k] = s;
    }

    uint32_t* dsth = g_cbf + (size_t)tile * 4096;
    int nt = sub * 2 + (grp >> 2);        // 0..15
    int kk = grp & 3;                     // 0..3
    int code = tile * 128 + nt * 8 + (lane >> 2);
    int k0 = kk * 16 + (lane & 3) * 2;
    const float* row = cb + (size_t)code * DIM;
    dsth[nt * 256 + lane * 8 + kk * 2 + 0] = packh2(row[k0], row[k0 + 1]);
    dsth[nt * 256 + lane * 8 + kk * 2 + 1] = packh2(row[k0 + 8], row[k0 + 9]);
}

// ---------------- main kernel (finalize folded in) ----------------
__global__ void __launch_bounds__(256, 3)
vq_main(const float* __restrict__ lat, const float* __restrict__ tgt,
        const float* __restrict__ cb, const float* __restrict__ dw,
        const float* __restrict__ db, float* __restrict__ out, int out_size) {
    extern __shared__ char sm[];
    float* As = (float*)(sm + A_OFF);
    const uint32_t smem_base = smem_u32(sm);
    uint32_t* scnt = (uint32_t*)(sm + CNT_OFF);
    unsigned long long* tokmin = (unsigned long long*)(sm + TOKMIN_OFF);
    const int tid = threadIdx.x;
    const int lane = tid & 31;
    const int w = tid >> 5;
    const int gid = lane >> 2;           // 0..7  token-row group
    const int tig = lane & 3;            // 0..3  col group
    const int blk = blockIdx.x;
    const int n = blk >> 4;              // image (16 blocks per image)
    const int hw0 = (blk & 15) * TOK_TILE;
    const int h = w & 1;                 // code half within tile
    const int tgrp = w >> 1;             // token group 0..3
    uint32_t* wl = (uint32_t*)(sm + LIST_OFF) + w * WLIST;

    if (tid < 192) ((float*)(sm + DW_OFF))[tid] = dw[tid];
    if (tid < 3)   ((float*)(sm + DB_OFF))[tid] = db[tid];
    if (tid < 8)   scnt[tid] = 0u;
    if (tid < TOK_TILE) tokmin[tid] = ~0ull;

    // ---- stage A (fp32) [k][token]: 64 k x 64 tokens ----
    const float* latbase = lat + (size_t)n * DIM * HW + hw0;
    {
        int tl = tid & 15;               // token-float4 index (0..15 -> 64 tokens)
        int cgrp = tid >> 4;             // 0..15
#pragma unroll
        for (int p = 0; p < 4; ++p) {
            int c = p * 16 + cgrp;
            float4 v = *(const float4*)(latbase + (size_t)c * HW + tl * 4);
            *(float4*)&As[c * A_STRIDE + tl * 4] = v;
        }
    }

    // ---- preload B tile 0 + cn tile 0 ----
    {
        const float4* src = (const float4*)(g_cbf);
        uint32_t dst = smem_base + B_OFF;
#pragma unroll 4
        for (int idx = tid; idx < 1024; idx += 256)
            cp16(dst + (uint32_t)idx * 16u, src + idx);
        if (tid < 32)
            cp16(smem_base + CN_OFF + (uint32_t)tid * 16u,
                 ((const float4*)g_cnorm) + tid);
        cp_commit();
    }
    cp_wait0();
    __syncthreads();

    // ---- resident A hi fragments (warp = 16 tokens x 64 codes) ----
    uint32_t ah[4][4];
    const int t0 = tgrp * 16 + gid;
#pragma unroll
    for (int kk = 0; kk < 4; ++kk) {
        int k0 = kk * 16 + tig * 2;
        ah[kk][0] = packh2(As[(k0 + 0) * A_STRIDE + t0],     As[(k0 + 1) * A_STRIDE + t0]);
        ah[kk][1] = packh2(As[(k0 + 0) * A_STRIDE + t0 + 8], As[(k0 + 1) * A_STRIDE + t0 + 8]);
        ah[kk][2] = packh2(As[(k0 + 8) * A_STRIDE + t0],     As[(k0 + 9) * A_STRIDE + t0]);
        ah[kk][3] = packh2(As[(k0 + 8) * A_STRIDE + t0 + 8], As[(k0 + 9) * A_STRIDE + t0 + 8]);
    }

    float minv0 = 3.4e38f, minv1 = 3.4e38f;

    // 17 iterations: tiles 0..15, then tile 0 again (appends enabled from i=1)
    for (int i = 0; i <= NTILES; ++i) {
        int cur = i & 1;
        if (i < NTILES) {
            int nxt = (i + 1 == NTILES) ? 0 : i + 1;
            const float4* src = (const float4*)(g_cbf + (size_t)nxt * 4096);
            uint32_t dst = smem_base + B_OFF + (uint32_t)(cur ^ 1) * B_BUF;
#pragma unroll 4
            for (int idx = tid; idx < 1024; idx += 256)
                cp16(dst + (uint32_t)idx * 16u, src + idx);
            if (tid < 32)
                cp16(smem_base + CN_OFF + (uint32_t)(cur ^ 1) * 512u + (uint32_t)tid * 16u,
                     ((const float4*)(g_cnorm + nxt * 128)) + tid);
            cp_commit();
        }

        const char* smB = sm + B_OFF + (uint32_t)cur * B_BUF;
        const float* cns = (const float*)(sm + CN_OFF + (uint32_t)cur * 512u);
        const int ti = (i == NTILES) ? 0 : i;
        const int cbase = ti * 128;
        const bool appending = (i > 0);
        const uint4* bp = (const uint4*)smB;   // uint4 index = nt*64 + lane*2

#pragma unroll
        for (int nto = 0; nto < 8; ++nto) {
            int nt = h * 8 + nto;
            uint4 q0 = bp[nt * 64 + lane * 2];       // kk0 (x,y), kk1 (z,w)
            uint4 q1 = bp[nt * 64 + lane * 2 + 1];   // kk2 (x,y), kk3 (z,w)

            float dA[4] = {0.f, 0.f, 0.f, 0.f};
            float dB[4] = {0.f, 0.f, 0.f, 0.f};
            mma_f16(dA, ah[0], q0.x, q0.y);
            mma_f16(dB, ah[2], q1.x, q1.y);
            mma_f16(dA, ah[1], q0.z, q0.w);
            mma_f16(dB, ah[3], q1.z, q1.w);

            float2 cn2 = *(const float2*)(cns + nt * 8 + tig * 2);
            int c0 = cbase + nt * 8 + tig * 2;
            float v0 = fmaf(-2.f, dA[0] + dB[0], cn2.x);
            float v1 = fmaf(-2.f, dA[1] + dB[1], cn2.y);
            float v2 = fmaf(-2.f, dA[2] + dB[2], cn2.x);
            float v3 = fmaf(-2.f, dA[3] + dB[3], cn2.y);

            float r0 = fminf(v0, v1);          // token t0
            float r1 = fminf(v2, v3);          // token t0+8
            bool pass = (r0 < minv0 + BMARG) | (r1 < minv1 + BMARG);
            if (appending) {
                if (__any_sync(0xFFFFFFFFu, pass)) {
                    float lim0 = minv0 + BMARG, lim1 = minv1 + BMARG;
                    if (v0 < lim0) { uint32_t p = atomicAdd(&scnt[w], 1u); if (p < WLIST) wl[p] = ((uint32_t)t0 << 11) | (uint32_t)c0; }
                    if (v1 < lim0) { uint32_t p = atomicAdd(&scnt[w], 1u); if (p < WLIST) wl[p] = ((uint32_t)t0 << 11) | (uint32_t)(c0 + 1); }
                    if (v2 < lim1) { uint32_t p = atomicAdd(&scnt[w], 1u); if (p < WLIST) wl[p] = ((uint32_t)(t0 + 8) << 11) | (uint32_t)c0; }
                    if (v3 < lim1) { uint32_t p = atomicAdd(&scnt[w], 1u); if (p < WLIST) wl[p] = ((uint32_t)(t0 + 8) << 11) | (uint32_t)(c0 + 1); }
                }
            }
            minv0 = fminf(minv0, r0);
            minv1 = fminf(minv1, r1);
        }
        // combine running min across the 4 col-threads of each token row
        minv0 = fminf(minv0, __shfl_xor_sync(0xFFFFFFFFu, minv0, 1));
        minv0 = fminf(minv0, __shfl_xor_sync(0xFFFFFFFFu, minv0, 2));
        minv1 = fminf(minv1, __shfl_xor_sync(0xFFFFFFFFu, minv1, 1));
        minv1 = fminf(minv1, __shfl_xor_sync(0xFFFFFFFFu, minv1, 2));

        cp_wait0();
        __syncthreads();
    }

    // ---- exact fp32 refinement (each warp refines its own list) ----
    {
        uint32_t mycnt = scnt[w];
        if (mycnt > WLIST) mycnt = WLIST;
        for (uint32_t idx = lane; idx < mycnt; idx += 32) {
            uint32_t e = wl[idx];
            int t = (int)(e >> 11);
            int c = (int)(e & 2047u);
            const float4* er = (const float4*)(cb + (size_t)c * DIM);
            float dot = 0.f;
#pragma unroll
            for (int k4 = 0; k4 < 16; ++k4) {
                float4 ev = er[k4];
                dot += ev.x * As[(k4 * 4 + 0) * A_STRIDE + t]
                     + ev.y * As[(k4 * 4 + 1) * A_STRIDE + t]
                     + ev.z * As[(k4 * 4 + 2) * A_STRIDE + t]
                     + ev.w * As[(k4 * 4 + 3) * A_STRIDE + t];
            }
            float val = g_cnorm[c] - 2.0f * dot;
            unsigned long long pk = ((unsigned long long)fkey(val) << 32) | (unsigned)c;
            atomicMin(&tokmin[t], pk);
        }
    }
    __syncthreads();

    // ---- exact fp32 epilogue ----
    float my_vq = 0.f, my_rc = 0.f;
    if (tid < TOK_TILE) {
        int bi = (int)(tokmin[tid] & 0xFFFFFFFFu);
        const float* q = cb + (size_t)bi * DIM;
        const float* dws = (const float*)(sm + DW_OFF);
        const float* dbs = (const float*)(sm + DB_OFF);
        float y0 = dbs[0], y1 = dbs[1], y2 = dbs[2];
        float vq = 0.f;
#pragma unroll
        for (int c4 = 0; c4 < DIM / 4; ++c4) {
            float4 qv = *(const float4*)(q + c4 * 4);
            float qa[4] = {qv.x, qv.y, qv.z, qv.w};
#pragma unroll
            for (int r = 0; r < 4; ++r) {
                int c = c4 * 4 + r;
                float xc = As[c * A_STRIDE + tid];
                float dd = xc - qa[r];
                vq += dd * dd;
                y0 += dws[c] * qa[r];
                y1 += dws[DIM + c] * qa[r];
                y2 += dws[2 * DIM + c] * qa[r];
            }
        }
        const float* tg = tgt + (size_t)n * 3 * HW + hw0 + tid;
        float e0 = y0 - tg[0];
        float e1 = y1 - tg[HW];
        float e2 = y2 - tg[2 * HW];
        my_vq = vq;
        my_rc = e0 * e0 + e1 * e1 + e2 * e2;
    }
    __syncthreads();
    float* sv = (float*)(sm + RED_OFF);
    float* sr = sv + 256;
    sv[tid] = my_vq;
    sr[tid] = my_rc;
    __syncthreads();
    for (int s = 128; s > 0; s >>= 1) {
        if (tid < s) { sv[tid] += sv[tid + s]; sr[tid] += sr[tid + s]; }
        __syncthreads();
    }
    if (tid == 0) {
        g_partial[blk] = sv[0];
        g_partial[NBLOCKS + blk] = sr[0];
    }

    // ---- last-block finalize (deterministic) ----
    __shared__ bool s_last;
    __threadfence();
    if (tid == 0) {
        unsigned v = atomicAdd(&g_done, 1u);
        s_last = (v == NBLOCKS - 1);
    }
    __syncthreads();
    if (s_last) {
        float v = g_partial[tid] + g_partial[256 + tid];
        float r = g_partial[NBLOCKS + tid] + g_partial[NBLOCKS + 256 + tid];
        __syncthreads();
        sv[tid] = v;
        sr[tid] = r;
        __syncthreads();
        for (int s = 128; s > 0; s >>= 1) {
            if (tid < s) { sv[tid] += sv[tid + s]; sr[tid] += sr[tid + s]; }
            __syncthreads();
        }
        for (int idx = tid; idx < out_size; idx += 256)
            if (idx >= 3) out[idx] = 0.f;
        if (tid == 0) {
            float vq_loss = 2.0f * sv[0] / (float)(NB * DIM * HW);
            float recon = sr[0] / (float)(NB * 3 * HW);
            if (out_size > 0) out[0] = vq_loss + recon;
            if (out_size > 1) out[1] = vq_loss;
            if (out_size > 2) out[2] = recon;
            g_done = 0;   // reset for next launch/replay
        }
    }
}

extern "C" void kernel_launch(void* const* d_in, const int* in_sizes, int n_in,
                              void* d_out, int out_size) {
    const float* lat = (const float*)d_in[0];
    const float* tgt = (const float*)d_in[1];
    const float* cb  = (const float*)d_in[2];
    const float* dw  = (const float*)d_in[3];
    const float* db  = (const float*)d_in[4];
    float* out = (float*)d_out;

    vq_prep<<<128, 256>>>(cb);

    cudaFuncSetAttribute(vq_main, cudaFuncAttributeMaxDynamicSharedMemorySize, SMEM_TOTAL);
    vq_main<<<NBLOCKS, 256, SMEM_TOTAL>>>(lat, tgt, cb, dw, db, out, out_size);
}

// round 12
// speedup vs baseline: 1.3373x; 1.3373x over previous
#include <cuda_runtime.h>
#include <cuda_fp16.h>
#include <cstdint>

// ---------------- problem constants ----------------
#define NB      32
#define DIM     64
#define HW      1024
#define KCODES  2048
#define TOK_TILE 128
#define NBLOCKS  256          // TOKENS / TOK_TILE
#define NTHREADS 512
#define NWARPS   16
#define NTILES   16           // KCODES / 128
#define BMARG    0.35f        // conservative |d2' - d_hi| bound (rigorous ~0.14)
#define WLIST    256          // per-warp candidate capacity

// ---------------- dynamic smem layout (bytes) ----------------
#define A_STRIDE 132
#define A_OFF    0u                       // fp32 A [64][132]  (33792 B)
#define B_OFF    33792u                   // 2 buffers x 16KB packed hi tiles
#define B_BUF    16384u
#define CN_OFF   66560u                   // 2 x 128 floats
#define DW_OFF   67584u                   // 192 floats
#define DB_OFF   68352u                   // 4 floats
#define CNT_OFF  68368u                   // 16 u32 per-warp counters
#define LIST_OFF 68432u                   // 16 x WLIST u32 (16384 B)
#define TOKMIN_OFF 84816u                 // 128 u64
#define RED_OFF  85840u                   // 2 x 512 floats
#define SMEM_TOTAL 89984u

__device__ float g_cnorm[KCODES];
__device__ float g_partial[2 * NBLOCKS];
__device__ unsigned int g_done = 0;
// packed fp16 HI codebook: per tile 4096 u32
// addr(u32) = nt*256 + lane*8 + kk*2 + r   (r: b0/b1 regs of m16n8k16 B frag)
__device__ uint32_t g_cbf[NTILES * 4096];

// ---------------- helpers ----------------
__device__ __forceinline__ uint32_t smem_u32(const void* p) {
    uint32_t a;
    asm("{ .reg .u64 t; cvta.to.shared.u64 t, %1; cvt.u32.u64 %0, t; }" : "=r"(a) : "l"(p));
    return a;
}
__device__ __forceinline__ uint32_t packh2(float x, float y) {
    __half2 h = __floats2half2_rn(x, y);
    return *reinterpret_cast<uint32_t*>(&h);
}
__device__ __forceinline__ void mma_f16(float* d, const uint32_t* a,
                                        uint32_t b0, uint32_t b1) {
    asm volatile(
        "mma.sync.aligned.m16n8k16.row.col.f32.f16.f16.f32 "
        "{%0,%1,%2,%3}, {%4,%5,%6,%7}, {%8,%9}, {%0,%1,%2,%3};"
        : "+f"(d[0]), "+f"(d[1]), "+f"(d[2]), "+f"(d[3])
        : "r"(a[0]), "r"(a[1]), "r"(a[2]), "r"(a[3]), "r"(b0), "r"(b1));
}
__device__ __forceinline__ void cp16(uint32_t s, const void* g) {
    asm volatile("cp.async.cg.shared.global [%0], [%1], 16;" :: "r"(s), "l"(g));
}
__device__ __forceinline__ void cp_commit() {
    asm volatile("cp.async.commit_group;" ::: "memory");
}
__device__ __forceinline__ void cp_wait0() {
    asm volatile("cp.async.wait_group 0;" ::: "memory");
}
__device__ __forceinline__ uint32_t fkey(float v) {
    uint32_t b = __float_as_uint(v);
    return (b & 0x80000000u) ? ~b : (b | 0x80000000u);
}

// ---------------- prep: codebook norms + packed fp16 hi tiles ----------------
// grid 128: blk = tile*8 + sub. sub packs nt = sub*2 + {0,1}; 16 cnorm rows.
__global__ void __launch_bounds__(256) vq_prep(const float* __restrict__ cb) {
    int blk = blockIdx.x;
    int tile = blk >> 3;
    int sub = blk & 7;
    int tid = threadIdx.x;
    int lane = tid & 31;
    int grp  = tid >> 5;                  // 0..7

    if (tid < 16) {
        int k = tile * 128 + sub * 16 + tid;
        const float* r = cb + (size_t)k * DIM;
        float s = 0.f;
#pragma unroll
        for (int c4 = 0; c4 < DIM / 4; ++c4) {
            float4 v = *(const float4*)(r + c4 * 4);
            s += v.x * v.x + v.y * v.y + v.z * v.z + v.w * v.w;
        }
        g_cnorm[k] = s;
    }

    uint32_t* dsth = g_cbf + (size_t)tile * 4096;
    int nt = sub * 2 + (grp >> 2);        // 0..15
    int kk = grp & 3;                     // 0..3
    int code = tile * 128 + nt * 8 + (lane >> 2);
    int k0 = kk * 16 + (lane & 3) * 2;
    const float* row = cb + (size_t)code * DIM;
    dsth[nt * 256 + lane * 8 + kk * 2 + 0] = packh2(row[k0], row[k0 + 1]);
    dsth[nt * 256 + lane * 8 + kk * 2 + 1] = packh2(row[k0 + 8], row[k0 + 9]);
}

// ---------------- main kernel (finalize folded in) ----------------
__global__ void __launch_bounds__(NTHREADS, 2)
vq_main(const float* __restrict__ lat, const float* __restrict__ tgt,
        const float* __restrict__ cb, const float* __restrict__ dw,
        const float* __restrict__ db, float* __restrict__ out, int out_size) {
    extern __shared__ char sm[];
    float* As = (float*)(sm + A_OFF);
    const uint32_t smem_base = smem_u32(sm);
    uint32_t* scnt = (uint32_t*)(sm + CNT_OFF);
    unsigned long long* tokmin = (unsigned long long*)(sm + TOKMIN_OFF);
    const int tid = threadIdx.x;
    const int lane = tid & 31;
    const int w = tid >> 5;              // 0..15
    const int gid = lane >> 2;           // 0..7  token-row group
    const int tig = lane & 3;            // 0..3  col group
    const int blk = blockIdx.x;
    const int n = blk >> 3;              // image (8 blocks per image)
    const int hw0 = (blk & 7) * TOK_TILE;
    const int h = w & 1;                 // code half within tile
    const int tgrp = w >> 1;             // token group 0..7
    uint32_t* wl = (uint32_t*)(sm + LIST_OFF) + w * WLIST;

    if (tid < 192) ((float*)(sm + DW_OFF))[tid] = dw[tid];
    if (tid < 3)   ((float*)(sm + DB_OFF))[tid] = db[tid];
    if (tid < NWARPS) scnt[tid] = 0u;
    if (tid < TOK_TILE) tokmin[tid] = ~0ull;

    // ---- stage A (fp32) [k][token]: 64 k x 128 tokens ----
    const float* latbase = lat + (size_t)n * DIM * HW + hw0;
    {
        int tl = tid & 31;               // token-float4 index
        int cgrp = tid >> 5;             // 0..15
#pragma unroll
        for (int p = 0; p < 4; ++p) {
            int c = p * 16 + cgrp;
            float4 v = *(const float4*)(latbase + (size_t)c * HW + tl * 4);
            *(float4*)&As[c * A_STRIDE + tl * 4] = v;
        }
    }

    // ---- preload B tile 0 + cn tile 0 ----
    {
        const float4* src = (const float4*)(g_cbf);
        uint32_t dst = smem_base + B_OFF;
#pragma unroll 2
        for (int idx = tid; idx < 1024; idx += NTHREADS)
            cp16(dst + (uint32_t)idx * 16u, src + idx);
        if (tid < 32)
            cp16(smem_base + CN_OFF + (uint32_t)tid * 16u,
                 ((const float4*)g_cnorm) + tid);
        cp_commit();
    }
    cp_wait0();
    __syncthreads();

    // ---- resident A hi fragments (warp = 16 tokens x 64 codes) ----
    uint32_t ah[4][4];
    const int t0 = tgrp * 16 + gid;
#pragma unroll
    for (int kk = 0; kk < 4; ++kk) {
        int k0 = kk * 16 + tig * 2;
        ah[kk][0] = packh2(As[(k0 + 0) * A_STRIDE + t0],     As[(k0 + 1) * A_STRIDE + t0]);
        ah[kk][1] = packh2(As[(k0 + 0) * A_STRIDE + t0 + 8], As[(k0 + 1) * A_STRIDE + t0 + 8]);
        ah[kk][2] = packh2(As[(k0 + 8) * A_STRIDE + t0],     As[(k0 + 9) * A_STRIDE + t0]);
        ah[kk][3] = packh2(As[(k0 + 8) * A_STRIDE + t0 + 8], As[(k0 + 9) * A_STRIDE + t0 + 8]);
    }

    float minv0 = 3.4e38f, minv1 = 3.4e38f;

    // 17 iterations: tiles 0..15, then tile 0 again (appends enabled from i=1)
    for (int i = 0; i <= NTILES; ++i) {
        int cur = i & 1;
        if (i < NTILES) {
            int nxt = (i + 1 == NTILES) ? 0 : i + 1;
            const float4* src = (const float4*)(g_cbf + (size_t)nxt * 4096);
            uint32_t dst = smem_base + B_OFF + (uint32_t)(cur ^ 1) * B_BUF;
#pragma unroll 2
            for (int idx = tid; idx < 1024; idx += NTHREADS)
                cp16(dst + (uint32_t)idx * 16u, src + idx);
            if (tid < 32)
                cp16(smem_base + CN_OFF + (uint32_t)(cur ^ 1) * 512u + (uint32_t)tid * 16u,
                     ((const float4*)(g_cnorm + nxt * 128)) + tid);
            cp_commit();
        }

        const char* smB = sm + B_OFF + (uint32_t)cur * B_BUF;
        const float* cns = (const float*)(sm + CN_OFF + (uint32_t)cur * 512u);
        const int ti = (i == NTILES) ? 0 : i;
        const int cbase = ti * 128;
        const bool appending = (i > 0);
        const uint4* bp = (const uint4*)smB;   // uint4 index = nt*64 + lane*2

#pragma unroll
        for (int nto = 0; nto < 8; ++nto) {
            int nt = h * 8 + nto;
            uint4 q0 = bp[nt * 64 + lane * 2];       // kk0 (x,y), kk1 (z,w)
            uint4 q1 = bp[nt * 64 + lane * 2 + 1];   // kk2 (x,y), kk3 (z,w)

            float dA[4] = {0.f, 0.f, 0.f, 0.f};
            float dB[4] = {0.f, 0.f, 0.f, 0.f};
            mma_f16(dA, ah[0], q0.x, q0.y);
            mma_f16(dB, ah[2], q1.x, q1.y);
            mma_f16(dA, ah[1], q0.z, q0.w);
            mma_f16(dB, ah[3], q1.z, q1.w);

            float2 cn2 = *(const float2*)(cns + nt * 8 + tig * 2);
            int c0 = cbase + nt * 8 + tig * 2;
            float v0 = fmaf(-2.f, dA[0] + dB[0], cn2.x);
            float v1 = fmaf(-2.f, dA[1] + dB[1], cn2.y);
            float v2 = fmaf(-2.f, dA[2] + dB[2], cn2.x);
            float v3 = fmaf(-2.f, dA[3] + dB[3], cn2.y);

            float r0 = fminf(v0, v1);          // token t0
            float r1 = fminf(v2, v3);          // token t0+8
            bool pass = (r0 < minv0 + BMARG) | (r1 < minv1 + BMARG);
            if (appending) {
                if (__any_sync(0xFFFFFFFFu, pass)) {
                    float lim0 = minv0 + BMARG, lim1 = minv1 + BMARG;
                    if (v0 < lim0) { uint32_t p = atomicAdd(&scnt[w], 1u); if (p < WLIST) wl[p] = ((uint32_t)t0 << 11) | (uint32_t)c0; }
                    if (v1 < lim0) { uint32_t p = atomicAdd(&scnt[w], 1u); if (p < WLIST) wl[p] = ((uint32_t)t0 << 11) | (uint32_t)(c0 + 1); }
                    if (v2 < lim1) { uint32_t p = atomicAdd(&scnt[w], 1u); if (p < WLIST) wl[p] = ((uint32_t)(t0 + 8) << 11) | (uint32_t)c0; }
                    if (v3 < lim1) { uint32_t p = atomicAdd(&scnt[w], 1u); if (p < WLIST) wl[p] = ((uint32_t)(t0 + 8) << 11) | (uint32_t)(c0 + 1); }
                }
            }
            minv0 = fminf(minv0, r0);
            minv1 = fminf(minv1, r1);
        }
        // combine running min across the 4 col-threads of each token row
        minv0 = fminf(minv0, __shfl_xor_sync(0xFFFFFFFFu, minv0, 1));
        minv0 = fminf(minv0, __shfl_xor_sync(0xFFFFFFFFu, minv0, 2));
        minv1 = fminf(minv1, __shfl_xor_sync(0xFFFFFFFFu, minv1, 1));
        minv1 = fminf(minv1, __shfl_xor_sync(0xFFFFFFFFu, minv1, 2));

        cp_wait0();
        __syncthreads();
    }

    // ---- exact fp32 refinement (each warp refines its own list) ----
    {
        uint32_t mycnt = scnt[w];
        if (mycnt > WLIST) mycnt = WLIST;
        for (uint32_t idx = lane; idx < mycnt; idx += 32) {
            uint32_t e = wl[idx];
            int t = (int)(e >> 11);
            int c = (int)(e & 2047u);
            const float4* er = (const float4*)(cb + (size_t)c * DIM);
            float dot = 0.f;
#pragma unroll
            for (int k4 = 0; k4 < 16; ++k4) {
                float4 ev = er[k4];
                dot += ev.x * As[(k4 * 4 + 0) * A_STRIDE + t]
                     + ev.y * As[(k4 * 4 + 1) * A_STRIDE + t]
                     + ev.z * As[(k4 * 4 + 2) * A_STRIDE + t]
                     + ev.w * As[(k4 * 4 + 3) * A_STRIDE + t];
            }
            float val = g_cnorm[c] - 2.0f * dot;
            unsigned long long pk = ((unsigned long long)fkey(val) << 32) | (unsigned)c;
            atomicMin(&tokmin[t], pk);
        }
    }
    __syncthreads();

    // ---- exact fp32 epilogue ----
    float my_vq = 0.f, my_rc = 0.f;
    if (tid < TOK_TILE) {
        int bi = (int)(tokmin[tid] & 0xFFFFFFFFu);
        const float* q = cb + (size_t)bi * DIM;
        const float* dws = (const float*)(sm + DW_OFF);
        const float* dbs = (const float*)(sm + DB_OFF);
        float y0 = dbs[0], y1 = dbs[1], y2 = dbs[2];
        float vq = 0.f;
#pragma unroll
        for (int c4 = 0; c4 < DIM / 4; ++c4) {
            float4 qv = *(const float4*)(q + c4 * 4);
            float qa[4] = {qv.x, qv.y, qv.z, qv.w};
#pragma unroll
            for (int r = 0; r < 4; ++r) {
                int c = c4 * 4 + r;
                float xc = As[c * A_STRIDE + tid];
                float dd = xc - qa[r];
                vq += dd * dd;
                y0 += dws[c] * qa[r];
                y1 += dws[DIM + c] * qa[r];
                y2 += dws[2 * DIM + c] * qa[r];
            }
        }
        const float* tg = tgt + (size_t)n * 3 * HW + hw0 + tid;
        float e0 = y0 - tg[0];
        float e1 = y1 - tg[HW];
        float e2 = y2 - tg[2 * HW];
        my_vq = vq;
        my_rc = e0 * e0 + e1 * e1 + e2 * e2;
    }
    __syncthreads();
    float* sv = (float*)(sm + RED_OFF);
    float* sr = sv + NTHREADS;
    sv[tid] = my_vq;
    sr[tid] = my_rc;
    __syncthreads();
    for (int s = NTHREADS / 2; s > 0; s >>= 1) {
        if (tid < s) { sv[tid] += sv[tid + s]; sr[tid] += sr[tid + s]; }
        __syncthreads();
    }
    if (tid == 0) {
        g_partial[blk] = sv[0];
        g_partial[NBLOCKS + blk] = sr[0];
    }

    // ---- last-block finalize (deterministic) ----
    __shared__ bool s_last;
    __threadfence();
    if (tid == 0) {
        unsigned v = atomicAdd(&g_done, 1u);
        s_last = (v == NBLOCKS - 1);
    }
    __syncthreads();
    if (s_last) {
        float v = (tid < NBLOCKS) ? g_partial[tid] : 0.f;
        float r = (tid < NBLOCKS) ? g_partial[NBLOCKS + tid] : 0.f;
        __syncthreads();
        sv[tid] = v;
        sr[tid] = r;
        __syncthreads();
        for (int s = NTHREADS / 2; s > 0; s >>= 1) {
            if (tid < s) { sv[tid] += sv[tid + s]; sr[tid] += sr[tid + s]; }
            __syncthreads();
        }
        for (int idx = tid; idx < out_size; idx += NTHREADS)
            if (idx >= 3) out[idx] = 0.f;
        if (tid == 0) {
            float vq_loss = 2.0f * sv[0] / (float)(NB * DIM * HW);
            float recon = sr[0] / (float)(NB * 3 * HW);
            if (out_size > 0) out[0] = vq_loss + recon;
            if (out_size > 1) out[1] = vq_loss;
            if (out_size > 2) out[2] = recon;
            g_done = 0;   // reset for next launch/replay
        }
    }
}

extern "C" void kernel_launch(void* const* d_in, const int* in_sizes, int n_in,
                              void* d_out, int out_size) {
    const float* lat = (const float*)d_in[0];
    const float* tgt = (const float*)d_in[1];
    const float* cb  = (const float*)d_in[2];
    const float* dw  = (const float*)d_in[3];
    const float* db  = (const float*)d_in[4];
    float* out = (float*)d_out;

    vq_prep<<<128, 256>>>(cb);

    cudaFuncSetAttribute(vq_main, cudaFuncAttributeMaxDynamicSharedMemorySize, SMEM_TOTAL);
    vq_main<<<NBLOCKS, NTHREADS, SMEM_TOTAL>>>(lat, tgt, cb, dw, db, out, out_size);
}

// round 13
// speedup vs baseline: 1.5179x; 1.1351x over previous
#include <cuda_runtime.h>
#include <cuda_fp16.h>
#include <cstdint>

// ---------------- problem constants ----------------
#define NB      32
#define DIM     64
#define HW      1024
#define KCODES  2048
#define TOK_TILE 128
#define NBLOCKS  256          // TOKENS / TOK_TILE
#define NTHREADS 512
#define NWARPS   16
#define NTILES   16           // KCODES / 128
#define BMARG    0.35f        // conservative |d2' - d_hi| bound (rigorous ~0.14)
#define WLIST    256          // per-warp candidate capacity

// ---------------- dynamic smem layout (bytes) ----------------
#define A_STRIDE 132
#define A_OFF    0u                       // fp32 A [64][132]  (33792 B)
#define B_OFF    33792u                   // 2 buffers x 16KB packed hi tiles
#define B_BUF    16384u
#define CN_OFF   66560u                   // 2 x 128 floats
#define DW_OFF   67584u                   // 192 floats
#define DB_OFF   68352u                   // 4 floats
#define CNT_OFF  68368u                   // 16 u32 per-warp counters
#define LIST_OFF 68432u                   // 16 x WLIST u32 (16384 B)
#define TOKMIN_OFF 84816u                 // 128 u64
#define RED_OFF  85840u                   // 2 x 512 floats
#define SMEM_TOTAL 89984u

__device__ float g_cnorm[KCODES];
__device__ float g_partial[2 * NBLOCKS];
__device__ unsigned int g_done = 0;
// packed fp16 HI codebook: per tile 4096 u32, TWO conflict-free regions:
//   region0 (u32 idx 0..2047):    [nt][lane] uint4 = kk0{b0,b1}, kk1{b0,b1}
//   region1 (u32 idx 2048..4095): [nt][lane] uint4 = kk2{b0,b1}, kk3{b0,b1}
// lane stride = 16B -> LDS.128 conflict-free.
__device__ uint32_t g_cbf[NTILES * 4096];

// ---------------- helpers ----------------
__device__ __forceinline__ uint32_t smem_u32(const void* p) {
    uint32_t a;
    asm("{ .reg .u64 t; cvta.to.shared.u64 t, %1; cvt.u32.u64 %0, t; }" : "=r"(a) : "l"(p));
    return a;
}
__device__ __forceinline__ uint32_t packh2(float x, float y) {
    __half2 h = __floats2half2_rn(x, y);
    return *reinterpret_cast<uint32_t*>(&h);
}
__device__ __forceinline__ void mma_f16(float* d, const uint32_t* a,
                                        uint32_t b0, uint32_t b1) {
    asm volatile(
        "mma.sync.aligned.m16n8k16.row.col.f32.f16.f16.f32 "
        "{%0,%1,%2,%3}, {%4,%5,%6,%7}, {%8,%9}, {%0,%1,%2,%3};"
        : "+f"(d[0]), "+f"(d[1]), "+f"(d[2]), "+f"(d[3])
        : "r"(a[0]), "r"(a[1]), "r"(a[2]), "r"(a[3]), "r"(b0), "r"(b1));
}
__device__ __forceinline__ void cp16(uint32_t s, const void* g) {
    asm volatile("cp.async.cg.shared.global [%0], [%1], 16;" :: "r"(s), "l"(g));
}
__device__ __forceinline__ void cp_commit() {
    asm volatile("cp.async.commit_group;" ::: "memory");
}
__device__ __forceinline__ void cp_wait0() {
    asm volatile("cp.async.wait_group 0;" ::: "memory");
}
__device__ __forceinline__ uint32_t fkey(float v) {
    uint32_t b = __float_as_uint(v);
    return (b & 0x80000000u) ? ~b : (b | 0x80000000u);
}

// ---------------- prep: codebook norms + packed fp16 hi tiles ----------------
// grid 128: blk = tile*8 + sub. sub packs nt = sub*2 + {0,1}; 16 cnorm rows.
__global__ void __launch_bounds__(256) vq_prep(const float* __restrict__ cb) {
    int blk = blockIdx.x;
    int tile = blk >> 3;
    int sub = blk & 7;
    int tid = threadIdx.x;
    int lane = tid & 31;
    int grp  = tid >> 5;                  // 0..7

    if (tid < 16) {
        int k = tile * 128 + sub * 16 + tid;
        const float* r = cb + (size_t)k * DIM;
        float s = 0.f;
#pragma unroll
        for (int c4 = 0; c4 < DIM / 4; ++c4) {
            float4 v = *(const float4*)(r + c4 * 4);
            s += v.x * v.x + v.y * v.y + v.z * v.z + v.w * v.w;
        }
        g_cnorm[k] = s;
    }

    uint32_t* dsth = g_cbf + (size_t)tile * 4096;
    int nt = sub * 2 + (grp >> 2);        // 0..15
    int kk = grp & 3;                     // 0..3
    int code = tile * 128 + nt * 8 + (lane >> 2);
    int k0 = kk * 16 + (lane & 3) * 2;
    const float* row = cb + (size_t)code * DIM;
    uint32_t b0 = packh2(row[k0], row[k0 + 1]);
    uint32_t b1 = packh2(row[k0 + 8], row[k0 + 9]);
    int region = (kk >> 1) * 2048;        // kk0/1 -> region0, kk2/3 -> region1
    int kslot = kk & 1;
    dsth[region + nt * 128 + lane * 4 + kslot * 2 + 0] = b0;
    dsth[region + nt * 128 + lane * 4 + kslot * 2 + 1] = b1;
}

// ---------------- main kernel (finalize folded in) ----------------
__global__ void __launch_bounds__(NTHREADS, 2)
vq_main(const float* __restrict__ lat, const float* __restrict__ tgt,
        const float* __restrict__ cb, const float* __restrict__ dw,
        const float* __restrict__ db, float* __restrict__ out, int out_size) {
    extern __shared__ char sm[];
    float* As = (float*)(sm + A_OFF);
    const uint32_t smem_base = smem_u32(sm);
    uint32_t* scnt = (uint32_t*)(sm + CNT_OFF);
    unsigned long long* tokmin = (unsigned long long*)(sm + TOKMIN_OFF);
    const int tid = threadIdx.x;
    const int lane = tid & 31;
    const int w = tid >> 5;              // 0..15
    const int gid = lane >> 2;           // 0..7  token-row group
    const int tig = lane & 3;            // 0..3  col group
    const int blk = blockIdx.x;
    const int n = blk >> 3;              // image (8 blocks per image)
    const int hw0 = (blk & 7) * TOK_TILE;
    const int h = w & 1;                 // code half within tile
    const int tgrp = w >> 1;             // token group 0..7
    uint32_t* wl = (uint32_t*)(sm + LIST_OFF) + w * WLIST;

    if (tid < 192) ((float*)(sm + DW_OFF))[tid] = dw[tid];
    if (tid < 3)   ((float*)(sm + DB_OFF))[tid] = db[tid];
    if (tid < NWARPS) scnt[tid] = 0u;
    if (tid < TOK_TILE) tokmin[tid] = ~0ull;

    // ---- stage A (fp32) [k][token]: 64 k x 128 tokens ----
    const float* latbase = lat + (size_t)n * DIM * HW + hw0;
    {
        int tl = tid & 31;               // token-float4 index
        int cgrp = tid >> 5;             // 0..15
#pragma unroll
        for (int p = 0; p < 4; ++p) {
            int c = p * 16 + cgrp;
            float4 v = *(const float4*)(latbase + (size_t)c * HW + tl * 4);
            *(float4*)&As[c * A_STRIDE + tl * 4] = v;
        }
    }

    // ---- preload B tile 0 + cn tile 0 ----
    {
        const float4* src = (const float4*)(g_cbf);
        uint32_t dst = smem_base + B_OFF;
#pragma unroll 2
        for (int idx = tid; idx < 1024; idx += NTHREADS)
            cp16(dst + (uint32_t)idx * 16u, src + idx);
        if (tid < 32)
            cp16(smem_base + CN_OFF + (uint32_t)tid * 16u,
                 ((const float4*)g_cnorm) + tid);
        cp_commit();
    }
    cp_wait0();
    __syncthreads();

    // ---- resident A hi fragments (warp = 16 tokens x 64 codes) ----
    uint32_t ah[4][4];
    const int t0 = tgrp * 16 + gid;
#pragma unroll
    for (int kk = 0; kk < 4; ++kk) {
        int k0 = kk * 16 + tig * 2;
        ah[kk][0] = packh2(As[(k0 + 0) * A_STRIDE + t0],     As[(k0 + 1) * A_STRIDE + t0]);
        ah[kk][1] = packh2(As[(k0 + 0) * A_STRIDE + t0 + 8], As[(k0 + 1) * A_STRIDE + t0 + 8]);
        ah[kk][2] = packh2(As[(k0 + 8) * A_STRIDE + t0],     As[(k0 + 9) * A_STRIDE + t0]);
        ah[kk][3] = packh2(As[(k0 + 8) * A_STRIDE + t0 + 8], As[(k0 + 9) * A_STRIDE + t0 + 8]);
    }

    float minv0 = 3.4e38f, minv1 = 3.4e38f;

    // 17 iterations: tiles 0..15, then tile 0 again (appends enabled from i=1)
    for (int i = 0; i <= NTILES; ++i) {
        int cur = i & 1;
        if (i < NTILES) {
            int nxt = (i + 1 == NTILES) ? 0 : i + 1;
            const float4* src = (const float4*)(g_cbf + (size_t)nxt * 4096);
            uint32_t dst = smem_base + B_OFF + (uint32_t)(cur ^ 1) * B_BUF;
#pragma unroll 2
            for (int idx = tid; idx < 1024; idx += NTHREADS)
                cp16(dst + (uint32_t)idx * 16u, src + idx);
            if (tid < 32)
                cp16(smem_base + CN_OFF + (uint32_t)(cur ^ 1) * 512u + (uint32_t)tid * 16u,
                     ((const float4*)(g_cnorm + nxt * 128)) + tid);
            cp_commit();
        }

        const char* smB = sm + B_OFF + (uint32_t)cur * B_BUF;
        const float* cns = (const float*)(sm + CN_OFF + (uint32_t)cur * 512u);
        const int ti = (i == NTILES) ? 0 : i;
        const int cbase = ti * 128;
        const bool appending = (i > 0);
        const uint4* bp0 = (const uint4*)smB;             // region0: [nt][lane]
        const uint4* bp1 = (const uint4*)(smB + 8192u);   // region1: [nt][lane]

#pragma unroll
        for (int nto = 0; nto < 8; ++nto) {
            int nt = h * 8 + nto;
            uint4 q0 = bp0[nt * 32 + lane];   // kk0 {b0,b1}, kk1 {b0,b1}
            uint4 q1 = bp1[nt * 32 + lane];   // kk2 {b0,b1}, kk3 {b0,b1}

            float dA[4] = {0.f, 0.f, 0.f, 0.f};
            float dB[4] = {0.f, 0.f, 0.f, 0.f};
            mma_f16(dA, ah[0], q0.x, q0.y);
            mma_f16(dB, ah[2], q1.x, q1.y);
            mma_f16(dA, ah[1], q0.z, q0.w);
            mma_f16(dB, ah[3], q1.z, q1.w);

            float2 cn2 = *(const float2*)(cns + nt * 8 + tig * 2);
            int c0 = cbase + nt * 8 + tig * 2;
            float v0 = fmaf(-2.f, dA[0] + dB[0], cn2.x);
            float v1 = fmaf(-2.f, dA[1] + dB[1], cn2.y);
            float v2 = fmaf(-2.f, dA[2] + dB[2], cn2.x);
            float v3 = fmaf(-2.f, dA[3] + dB[3], cn2.y);

            float r0 = fminf(v0, v1);          // token t0
            float r1 = fminf(v2, v3);          // token t0+8
            bool pass = (r0 < minv0 + BMARG) | (r1 < minv1 + BMARG);
            if (appending) {
                if (__any_sync(0xFFFFFFFFu, pass)) {
                    float lim0 = minv0 + BMARG, lim1 = minv1 + BMARG;
                    if (v0 < lim0) { uint32_t p = atomicAdd(&scnt[w], 1u); if (p < WLIST) wl[p] = ((uint32_t)t0 << 11) | (uint32_t)c0; }
                    if (v1 < lim0) { uint32_t p = atomicAdd(&scnt[w], 1u); if (p < WLIST) wl[p] = ((uint32_t)t0 << 11) | (uint32_t)(c0 + 1); }
                    if (v2 < lim1) { uint32_t p = atomicAdd(&scnt[w], 1u); if (p < WLIST) wl[p] = ((uint32_t)(t0 + 8) << 11) | (uint32_t)c0; }
                    if (v3 < lim1) { uint32_t p = atomicAdd(&scnt[w], 1u); if (p < WLIST) wl[p] = ((uint32_t)(t0 + 8) << 11) | (uint32_t)(c0 + 1); }
                }
            }
            minv0 = fminf(minv0, r0);
            minv1 = fminf(minv1, r1);
        }
        // combine running min across the 4 col-threads of each token row
        minv0 = fminf(minv0, __shfl_xor_sync(0xFFFFFFFFu, minv0, 1));
        minv0 = fminf(minv0, __shfl_xor_sync(0xFFFFFFFFu, minv0, 2));
        minv1 = fminf(minv1, __shfl_xor_sync(0xFFFFFFFFu, minv1, 1));
        minv1 = fminf(minv1, __shfl_xor_sync(0xFFFFFFFFu, minv1, 2));

        cp_wait0();
        __syncthreads();
    }

    // ---- exact fp32 refinement (each warp refines its own list) ----
    {
        uint32_t mycnt = scnt[w];
        if (mycnt > WLIST) mycnt = WLIST;
        for (uint32_t idx = lane; idx < mycnt; idx += 32) {
            uint32_t e = wl[idx];
            int t = (int)(e >> 11);
            int c = (int)(e & 2047u);
            const float4* er = (const float4*)(cb + (size_t)c * DIM);
            float dot = 0.f;
#pragma unroll
            for (int k4 = 0; k4 < 16; ++k4) {
                float4 ev = er[k4];
                dot += ev.x * As[(k4 * 4 + 0) * A_STRIDE + t]
                     + ev.y * As[(k4 * 4 + 1) * A_STRIDE + t]
                     + ev.z * As[(k4 * 4 + 2) * A_STRIDE + t]
                     + ev.w * As[(k4 * 4 + 3) * A_STRIDE + t];
            }
            float val = g_cnorm[c] - 2.0f * dot;
            unsigned long long pk = ((unsigned long long)fkey(val) << 32) | (unsigned)c;
            atomicMin(&tokmin[t], pk);
        }
    }
    __syncthreads();

    // ---- exact fp32 epilogue ----
    float my_vq = 0.f, my_rc = 0.f;
    if (tid < TOK_TILE) {
        int bi = (int)(tokmin[tid] & 0xFFFFFFFFu);
        const float* q = cb + (size_t)bi * DIM;
        const float* dws = (const float*)(sm + DW_OFF);
        const float* dbs = (const float*)(sm + DB_OFF);
        float y0 = dbs[0], y1 = dbs[1], y2 = dbs[2];
        float vq = 0.f;
#pragma unroll
        for (int c4 = 0; c4 < DIM / 4; ++c4) {
            float4 qv = *(const float4*)(q + c4 * 4);
            float qa[4] = {qv.x, qv.y, qv.z, qv.w};
#pragma unroll
            for (int r = 0; r < 4; ++r) {
                int c = c4 * 4 + r;
                float xc = As[c * A_STRIDE + tid];
                float dd = xc - qa[r];
                vq += dd * dd;
                y0 += dws[c] * qa[r];
                y1 += dws[DIM + c] * qa[r];
                y2 += dws[2 * DIM + c] * qa[r];
            }
        }
        const float* tg = tgt + (size_t)n * 3 * HW + hw0 + tid;
        float e0 = y0 - tg[0];
        float e1 = y1 - tg[HW];
        float e2 = y2 - tg[2 * HW];
        my_vq = vq;
        my_rc = e0 * e0 + e1 * e1 + e2 * e2;
    }
    __syncthreads();
    float* sv = (float*)(sm + RED_OFF);
    float* sr = sv + NTHREADS;
    sv[tid] = my_vq;
    sr[tid] = my_rc;
    __syncthreads();
    for (int s = NTHREADS / 2; s > 0; s >>= 1) {
        if (tid < s) { sv[tid] += sv[tid + s]; sr[tid] += sr[tid + s]; }
        __syncthreads();
    }
    if (tid == 0) {
        g_partial[blk] = sv[0];
        g_partial[NBLOCKS + blk] = sr[0];
    }

    // ---- last-block finalize (deterministic) ----
    __shared__ bool s_last;
    __threadfence();
    if (tid == 0) {
        unsigned v = atomicAdd(&g_done, 1u);
        s_last = (v == NBLOCKS - 1);
    }
    __syncthreads();
    if (s_last) {
        float v = (tid < NBLOCKS) ? g_partial[tid] : 0.f;
        float r = (tid < NBLOCKS) ? g_partial[NBLOCKS + tid] : 0.f;
        __syncthreads();
        sv[tid] = v;
        sr[tid] = r;
        __syncthreads();
        for (int s = NTHREADS / 2; s > 0; s >>= 1) {
            if (tid < s) { sv[tid] += sv[tid + s]; sr[tid] += sr[tid + s]; }
            __syncthreads();
        }
        for (int idx = tid; idx < out_size; idx += NTHREADS)
            if (idx >= 3) out[idx] = 0.f;
        if (tid == 0) {
            float vq_loss = 2.0f * sv[0] / (float)(NB * DIM * HW);
            float recon = sr[0] / (float)(NB * 3 * HW);
            if (out_size > 0) out[0] = vq_loss + recon;
            if (out_size > 1) out[1] = vq_loss;
            if (out_size > 2) out[2] = recon;
            g_done = 0;   // reset for next launch/replay
        }
    }
}

extern "C" void kernel_launch(void* const* d_in, const int* in_sizes, int n_in,
                              void* d_out, int out_size) {
    const float* lat = (const float*)d_in[0];
    const float* tgt = (const float*)d_in[1];
    const float* cb  = (const float*)d_in[2];
    const float* dw  = (const float*)d_in[3];
    const float* db  = (const float*)d_in[4];
    float* out = (float*)d_out;

    vq_prep<<<128, 256>>>(cb);

    cudaFuncSetAttribute(vq_main, cudaFuncAttributeMaxDynamicSharedMemorySize, SMEM_TOTAL);
    vq_main<<<NBLOCKS, NTHREADS, SMEM_TOTAL>>>(lat, tgt, cb, dw, db, out, out_size);
}

// round 14
// speedup vs baseline: 1.5381x; 1.0133x over previous
#include <cuda_runtime.h>
#include <cuda_fp16.h>
#include <cstdint>

// ---------------- problem constants ----------------
#define NB      32
#define DIM     64
#define HW      1024
#define KCODES  2048
#define TOK_TILE 128
#define NBLOCKS  256          // TOKENS / TOK_TILE
#define NTHREADS 512
#define NWARPS   16
#define NTILES   16           // KCODES / 128
#define HMARG    0.175f       // d-space margin = BMARG/2 (v-space 0.35, rigorous ~0.14)
#define WLIST    256          // per-warp candidate capacity

// ---------------- dynamic smem layout (bytes) ----------------
#define A_STRIDE 132
#define A_OFF    0u                       // fp32 A [64][132]  (33792 B)
#define B_OFF    33792u                   // 2 buffers x 16KB packed hi tiles
#define B_BUF    16384u
#define CN_OFF   66560u                   // 2 x 128 floats (-0.5*cn)
#define DW_OFF   67584u                   // 192 floats
#define DB_OFF   68352u                   // 4 floats
#define CNT_OFF  68368u                   // 16 u32 per-warp counters
#define LIST_OFF 68432u                   // 16 x WLIST u32 (16384 B)
#define TOKMIN_OFF 84816u                 // 128 u64
#define RED_OFF  85840u                   // 2 x 512 floats
#define SMEM_TOTAL 89984u

__device__ float g_cnorm[KCODES];         // exact ||e||^2 (refine path)
__device__ float g_cnh[KCODES];           // -0.5 * ||e||^2 (screen accum init)
__device__ float g_partial[2 * NBLOCKS];
__device__ unsigned int g_done = 0;
// packed fp16 HI codebook: per tile 4096 u32, TWO conflict-free regions:
//   region0 (u32 idx 0..2047):    [nt][lane] uint4 = kk0{b0,b1}, kk1{b0,b1}
//   region1 (u32 idx 2048..4095): [nt][lane] uint4 = kk2{b0,b1}, kk3{b0,b1}
// lane stride = 16B -> LDS.128 conflict-free.
__device__ uint32_t g_cbf[NTILES * 4096];

// ---------------- helpers ----------------
__device__ __forceinline__ uint32_t smem_u32(const void* p) {
    uint32_t a;
    asm("{ .reg .u64 t; cvta.to.shared.u64 t, %1; cvt.u32.u64 %0, t; }" : "=r"(a) : "l"(p));
    return a;
}
__device__ __forceinline__ uint32_t packh2(float x, float y) {
    __half2 h = __floats2half2_rn(x, y);
    return *reinterpret_cast<uint32_t*>(&h);
}
__device__ __forceinline__ void mma_f16(float* d, const uint32_t* a,
                                        uint32_t b0, uint32_t b1) {
    asm volatile(
        "mma.sync.aligned.m16n8k16.row.col.f32.f16.f16.f32 "
        "{%0,%1,%2,%3}, {%4,%5,%6,%7}, {%8,%9}, {%0,%1,%2,%3};"
        : "+f"(d[0]), "+f"(d[1]), "+f"(d[2]), "+f"(d[3])
        : "r"(a[0]), "r"(a[1]), "r"(a[2]), "r"(a[3]), "r"(b0), "r"(b1));
}
__device__ __forceinline__ void cp16(uint32_t s, const void* g) {
    asm volatile("cp.async.cg.shared.global [%0], [%1], 16;" :: "r"(s), "l"(g));
}
__device__ __forceinline__ void cp_commit() {
    asm volatile("cp.async.commit_group;" ::: "memory");
}
__device__ __forceinline__ void cp_wait0() {
    asm volatile("cp.async.wait_group 0;" ::: "memory");
}
__device__ __forceinline__ uint32_t fkey(float v) {
    uint32_t b = __float_as_uint(v);
    return (b & 0x80000000u) ? ~b : (b | 0x80000000u);
}

// ---------------- prep: codebook norms + packed fp16 hi tiles ----------------
// grid 128: blk = tile*8 + sub. sub packs nt = sub*2 + {0,1}; 16 cnorm rows.
__global__ void __launch_bounds__(256) vq_prep(const float* __restrict__ cb) {
    int blk = blockIdx.x;
    int tile = blk >> 3;
    int sub = blk & 7;
    int tid = threadIdx.x;
    int lane = tid & 31;
    int grp  = tid >> 5;                  // 0..7

    if (tid < 16) {
        int k = tile * 128 + sub * 16 + tid;
        const float* r = cb + (size_t)k * DIM;
        float s = 0.f;
#pragma unroll
        for (int c4 = 0; c4 < DIM / 4; ++c4) {
            float4 v = *(const float4*)(r + c4 * 4);
            s += v.x * v.x + v.y * v.y + v.z * v.z + v.w * v.w;
        }
        g_cnorm[k] = s;
        g_cnh[k] = -0.5f * s;
    }

    uint32_t* dsth = g_cbf + (size_t)tile * 4096;
    int nt = sub * 2 + (grp >> 2);        // 0..15
    int kk = grp & 3;                     // 0..3
    int code = tile * 128 + nt * 8 + (lane >> 2);
    int k0 = kk * 16 + (lane & 3) * 2;
    const float* row = cb + (size_t)code * DIM;
    uint32_t b0 = packh2(row[k0], row[k0 + 1]);
    uint32_t b1 = packh2(row[k0 + 8], row[k0 + 9]);
    int region = (kk >> 1) * 2048;        // kk0/1 -> region0, kk2/3 -> region1
    int kslot = kk & 1;
    dsth[region + nt * 128 + lane * 4 + kslot * 2 + 0] = b0;
    dsth[region + nt * 128 + lane * 4 + kslot * 2 + 1] = b1;
}

// ---------------- main kernel (finalize folded in) ----------------
__global__ void __launch_bounds__(NTHREADS, 2)
vq_main(const float* __restrict__ lat, const float* __restrict__ tgt,
        const float* __restrict__ cb, const float* __restrict__ dw,
        const float* __restrict__ db, float* __restrict__ out, int out_size) {
    extern __shared__ char sm[];
    float* As = (float*)(sm + A_OFF);
    const uint32_t smem_base = smem_u32(sm);
    uint32_t* scnt = (uint32_t*)(sm + CNT_OFF);
    unsigned long long* tokmin = (unsigned long long*)(sm + TOKMIN_OFF);
    const int tid = threadIdx.x;
    const int lane = tid & 31;
    const int w = tid >> 5;              // 0..15
    const int gid = lane >> 2;           // 0..7  token-row group
    const int tig = lane & 3;            // 0..3  col group
    const int blk = blockIdx.x;
    const int n = blk >> 3;              // image (8 blocks per image)
    const int hw0 = (blk & 7) * TOK_TILE;
    const int h = w & 1;                 // code half within tile
    const int tgrp = w >> 1;             // token group 0..7
    uint32_t* wl = (uint32_t*)(sm + LIST_OFF) + w * WLIST;

    if (tid < 192) ((float*)(sm + DW_OFF))[tid] = dw[tid];
    if (tid < 3)   ((float*)(sm + DB_OFF))[tid] = db[tid];
    if (tid < NWARPS) scnt[tid] = 0u;
    if (tid < TOK_TILE) tokmin[tid] = ~0ull;

    // ---- stage A (fp32) [k][token]: 64 k x 128 tokens ----
    const float* latbase = lat + (size_t)n * DIM * HW + hw0;
    {
        int tl = tid & 31;               // token-float4 index
        int cgrp = tid >> 5;             // 0..15
#pragma unroll
        for (int p = 0; p < 4; ++p) {
            int c = p * 16 + cgrp;
            float4 v = *(const float4*)(latbase + (size_t)c * HW + tl * 4);
            *(float4*)&As[c * A_STRIDE + tl * 4] = v;
        }
    }

    // ---- preload B tile 0 + cnh tile 0 ----
    {
        const float4* src = (const float4*)(g_cbf);
        uint32_t dst = smem_base + B_OFF;
#pragma unroll 2
        for (int idx = tid; idx < 1024; idx += NTHREADS)
            cp16(dst + (uint32_t)idx * 16u, src + idx);
        if (tid < 32)
            cp16(smem_base + CN_OFF + (uint32_t)tid * 16u,
                 ((const float4*)g_cnh) + tid);
        cp_commit();
    }
    cp_wait0();
    __syncthreads();

    // ---- resident A hi fragments (warp = 16 tokens x 64 codes) ----
    uint32_t ah[4][4];
    const int t0 = tgrp * 16 + gid;
#pragma unroll
    for (int kk = 0; kk < 4; ++kk) {
        int k0 = kk * 16 + tig * 2;
        ah[kk][0] = packh2(As[(k0 + 0) * A_STRIDE + t0],     As[(k0 + 1) * A_STRIDE + t0]);
        ah[kk][1] = packh2(As[(k0 + 0) * A_STRIDE + t0 + 8], As[(k0 + 1) * A_STRIDE + t0 + 8]);
        ah[kk][2] = packh2(As[(k0 + 8) * A_STRIDE + t0],     As[(k0 + 9) * A_STRIDE + t0]);
        ah[kk][3] = packh2(As[(k0 + 8) * A_STRIDE + t0 + 8], As[(k0 + 9) * A_STRIDE + t0 + 8]);
    }

    // running MAX of d = -0.5*v per token row (bigger d = closer code)
    float maxd0 = -3.4e38f, maxd1 = -3.4e38f;

    // 17 iterations: tiles 0..15, then tile 0 again (appends enabled from i=1)
    for (int i = 0; i <= NTILES; ++i) {
        int cur = i & 1;
        if (i < NTILES) {
            int nxt = (i + 1 == NTILES) ? 0 : i + 1;
            const float4* src = (const float4*)(g_cbf + (size_t)nxt * 4096);
            uint32_t dst = smem_base + B_OFF + (uint32_t)(cur ^ 1) * B_BUF;
#pragma unroll 2
            for (int idx = tid; idx < 1024; idx += NTHREADS)
                cp16(dst + (uint32_t)idx * 16u, src + idx);
            if (tid < 32)
                cp16(smem_base + CN_OFF + (uint32_t)(cur ^ 1) * 512u + (uint32_t)tid * 16u,
                     ((const float4*)(g_cnh + nxt * 128)) + tid);
            cp_commit();
        }

        const char* smB = sm + B_OFF + (uint32_t)cur * B_BUF;
        const float* cns = (const float*)(sm + CN_OFF + (uint32_t)cur * 512u);
        const int ti = (i == NTILES) ? 0 : i;
        const int cbase = ti * 128;
        const bool appending = (i > 0);
        const uint4* bp0 = (const uint4*)smB;             // region0: [nt][lane]
        const uint4* bp1 = (const uint4*)(smB + 8192u);   // region1: [nt][lane]

#pragma unroll
        for (int nto = 0; nto < 8; ++nto) {
            int nt = h * 8 + nto;
            uint4 q0 = bp0[nt * 32 + lane];   // kk0 {b0,b1}, kk1 {b0,b1}
            uint4 q1 = bp1[nt * 32 + lane];   // kk2 {b0,b1}, kk3 {b0,b1}
            float2 cnh = *(const float2*)(cns + nt * 8 + tig * 2);   // -0.5*cn

            // single chained accumulator, init = -0.5*cn  ->  d = dot - 0.5*cn = -0.5*v
            float d[4] = {cnh.x, cnh.y, cnh.x, cnh.y};
            mma_f16(d, ah[0], q0.x, q0.y);
            mma_f16(d, ah[1], q0.z, q0.w);
            mma_f16(d, ah[2], q1.x, q1.y);
            mma_f16(d, ah[3], q1.z, q1.w);

            int c0 = cbase + nt * 8 + tig * 2;
            float r0 = fmaxf(d[0], d[1]);      // token t0
            float r1 = fmaxf(d[2], d[3]);      // token t0+8
            bool pass = (r0 > maxd0 - HMARG) | (r1 > maxd1 - HMARG);
            if (appending) {
                if (__any_sync(0xFFFFFFFFu, pass)) {
                    float lim0 = maxd0 - HMARG, lim1 = maxd1 - HMARG;
                    if (d[0] > lim0) { uint32_t p = atomicAdd(&scnt[w], 1u); if (p < WLIST) wl[p] = ((uint32_t)t0 << 11) | (uint32_t)c0; }
                    if (d[1] > lim0) { uint32_t p = atomicAdd(&scnt[w], 1u); if (p < WLIST) wl[p] = ((uint32_t)t0 << 11) | (uint32_t)(c0 + 1); }
                    if (d[2] > lim1) { uint32_t p = atomicAdd(&scnt[w], 1u); if (p < WLIST) wl[p] = ((uint32_t)(t0 + 8) << 11) | (uint32_t)c0; }
                    if (d[3] > lim1) { uint32_t p = atomicAdd(&scnt[w], 1u); if (p < WLIST) wl[p] = ((uint32_t)(t0 + 8) << 11) | (uint32_t)(c0 + 1); }
                }
            }
            maxd0 = fmaxf(maxd0, r0);
            maxd1 = fmaxf(maxd1, r1);
        }
        // combine running max across the 4 col-threads of each token row
        maxd0 = fmaxf(maxd0, __shfl_xor_sync(0xFFFFFFFFu, maxd0, 1));
        maxd0 = fmaxf(maxd0, __shfl_xor_sync(0xFFFFFFFFu, maxd0, 2));
        maxd1 = fmaxf(maxd1, __shfl_xor_sync(0xFFFFFFFFu, maxd1, 1));
        maxd1 = fmaxf(maxd1, __shfl_xor_sync(0xFFFFFFFFu, maxd1, 2));

        cp_wait0();
        __syncthreads();
    }

    // ---- exact fp32 refinement (each warp refines its own list) ----
    {
        uint32_t mycnt = scnt[w];
        if (mycnt > WLIST) mycnt = WLIST;
        for (uint32_t idx = lane; idx < mycnt; idx += 32) {
            uint32_t e = wl[idx];
            int t = (int)(e >> 11);
            int c = (int)(e & 2047u);
            const float4* er = (const float4*)(cb + (size_t)c * DIM);
            float dot = 0.f;
#pragma unroll
            for (int k4 = 0; k4 < 16; ++k4) {
                float4 ev = er[k4];
                dot += ev.x * As[(k4 * 4 + 0) * A_STRIDE + t]
                     + ev.y * As[(k4 * 4 + 1) * A_STRIDE + t]
                     + ev.z * As[(k4 * 4 + 2) * A_STRIDE + t]
                     + ev.w * As[(k4 * 4 + 3) * A_STRIDE + t];
            }
            float val = g_cnorm[c] - 2.0f * dot;
            unsigned long long pk = ((unsigned long long)fkey(val) << 32) | (unsigned)c;
            atomicMin(&tokmin[t], pk);
        }
    }
    __syncthreads();

    // ---- exact fp32 epilogue ----
    float my_vq = 0.f, my_rc = 0.f;
    if (tid < TOK_TILE) {
        int bi = (int)(tokmin[tid] & 0xFFFFFFFFu);
        const float* q = cb + (size_t)bi * DIM;
        const float* dws = (const float*)(sm + DW_OFF);
        const float* dbs = (const float*)(sm + DB_OFF);
        float y0 = dbs[0], y1 = dbs[1], y2 = dbs[2];
        float vq = 0.f;
#pragma unroll
        for (int c4 = 0; c4 < DIM / 4; ++c4) {
            float4 qv = *(const float4*)(q + c4 * 4);
            float qa[4] = {qv.x, qv.y, qv.z, qv.w};
#pragma unroll
            for (int r = 0; r < 4; ++r) {
                int c = c4 * 4 + r;
                float xc = As[c * A_STRIDE + tid];
                float dd = xc - qa[r];
                vq += dd * dd;
                y0 += dws[c] * qa[r];
                y1 += dws[DIM + c] * qa[r];
                y2 += dws[2 * DIM + c] * qa[r];
            }
        }
        const float* tg = tgt + (size_t)n * 3 * HW + hw0 + tid;
        float e0 = y0 - tg[0];
        float e1 = y1 - tg[HW];
        float e2 = y2 - tg[2 * HW];
        my_vq = vq;
        my_rc = e0 * e0 + e1 * e1 + e2 * e2;
    }
    __syncthreads();
    float* sv = (float*)(sm + RED_OFF);
    float* sr = sv + NTHREADS;
    sv[tid] = my_vq;
    sr[tid] = my_rc;
    __syncthreads();
    for (int s = NTHREADS / 2; s > 0; s >>= 1) {
        if (tid < s) { sv[tid] += sv[tid + s]; sr[tid] += sr[tid + s]; }
        __syncthreads();
    }
    if (tid == 0) {
        g_partial[blk] = sv[0];
        g_partial[NBLOCKS + blk] = sr[0];
    }

    // ---- last-block finalize (deterministic) ----
    __shared__ bool s_last;
    __threadfence();
    if (tid == 0) {
        unsigned v = atomicAdd(&g_done, 1u);
        s_last = (v == NBLOCKS - 1);
    }
    __syncthreads();
    if (s_last) {
        float v = (tid < NBLOCKS) ? g_partial[tid] : 0.f;
        float r = (tid < NBLOCKS) ? g_partial[NBLOCKS + tid] : 0.f;
        __syncthreads();
        sv[tid] = v;
        sr[tid] = r;
        __syncthreads();
        for (int s = NTHREADS / 2; s > 0; s >>= 1) {
            if (tid < s) { sv[tid] += sv[tid + s]; sr[tid] += sr[tid + s]; }
            __syncthreads();
        }
        for (int idx = tid; idx < out_size; idx += NTHREADS)
            if (idx >= 3) out[idx] = 0.f;
        if (tid == 0) {
            float vq_loss = 2.0f * sv[0] / (float)(NB * DIM * HW);
            float recon = sr[0] / (float)(NB * 3 * HW);
            if (out_size > 0) out[0] = vq_loss + recon;
            if (out_size > 1) out[1] = vq_loss;
            if (out_size > 2) out[2] = recon;
            g_done = 0;   // reset for next launch/replay
        }
    }
}

extern "C" void kernel_launch(void* const* d_in, const int* in_sizes, int n_in,
                              void* d_out, int out_size) {
    const float* lat = (const float*)d_in[0];
    const float* tgt = (const float*)d_in[1];
    const float* cb  = (const float*)d_in[2];
    const float* dw  = (const float*)d_in[3];
    const float* db  = (const float*)d_in[4];
    float* out = (float*)d_out;

    vq_prep<<<128, 256>>>(cb);

    cudaFuncSetAttribute(vq_main, cudaFuncAttributeMaxDynamicSharedMemorySize, SMEM_TOTAL);
    vq_main<<<NBLOCKS, NTHREADS, SMEM_TOTAL>>>(lat, tgt, cb, dw, db, out, out_size);
}

// round 15
// speedup vs baseline: 1.7018x; 1.1065x over previous
#include <cuda_runtime.h>
#include <cuda_fp16.h>
#include <cstdint>

// ---------------- problem constants ----------------
#define NB      32
#define DIM     64
#define HW      1024
#define KCODES  2048
#define TOK_TILE 128
#define NBLOCKS  256          // TOKENS / TOK_TILE
#define NTHREADS 256
#define NWARPS   8
#define NTILES   16           // KCODES / 128
#define HMARG    0.175f       // d-space margin = v-space 0.35 / 2 (rigorous ~0.07)
#define WLIST    512          // per-warp candidate capacity

// ---------------- dynamic smem layout (bytes) ----------------
#define A_STRIDE 132
#define A_OFF    0u                       // fp32 A [64][132]  (33792 B)
#define B_OFF    33792u                   // 2 buffers x 16KB packed hi tiles
#define B_BUF    16384u
#define CN_OFF   66560u                   // 2 x 128 floats (packed -0.5*cn, nt-pair layout)
#define DW_OFF   67584u                   // 192 floats
#define DB_OFF   68352u                   // 4 floats
#define CNT_OFF  68368u                   // 8 u32 per-warp counters
#define LIST_OFF 68400u                   // 8 x WLIST u32 (16384 B)
#define TOKMIN_OFF 84784u                 // 128 u64
#define RED_OFF  85808u                   // 2 x 256 floats
#define SMEM_TOTAL 87856u

__device__ float g_cnorm[KCODES];         // exact ||e||^2 (refine path)
// packed -0.5*cn, per tile 128 floats: [ntp 8][tig 4] float4 =
//   { cnh(nt0,tig*2), cnh(nt0,tig*2+1), cnh(nt1,tig*2), cnh(nt1,tig*2+1) }, nt0=2*ntp
__device__ float g_cnp[NTILES * 128];
__device__ float g_partial[2 * NBLOCKS];
__device__ unsigned int g_done = 0;
// packed fp16 HI codebook: per tile 4096 u32, TWO conflict-free regions:
//   region0 (u32 0..2047):    [nt][lane] uint4 = kk0{b0,b1}, kk1{b0,b1}
//   region1 (u32 2048..4095): [nt][lane] uint4 = kk2{b0,b1}, kk3{b0,b1}
__device__ uint32_t g_cbf[NTILES * 4096];

// ---------------- helpers ----------------
__device__ __forceinline__ uint32_t smem_u32(const void* p) {
    uint32_t a;
    asm("{ .reg .u64 t; cvta.to.shared.u64 t, %1; cvt.u32.u64 %0, t; }" : "=r"(a) : "l"(p));
    return a;
}
__device__ __forceinline__ uint32_t packh2(float x, float y) {
    __half2 h = __floats2half2_rn(x, y);
    return *reinterpret_cast<uint32_t*>(&h);
}
__device__ __forceinline__ void mma_f16(float* d, const uint32_t* a,
                                        uint32_t b0, uint32_t b1) {
    asm volatile(
        "mma.sync.aligned.m16n8k16.row.col.f32.f16.f16.f32 "
        "{%0,%1,%2,%3}, {%4,%5,%6,%7}, {%8,%9}, {%0,%1,%2,%3};"
        : "+f"(d[0]), "+f"(d[1]), "+f"(d[2]), "+f"(d[3])
        : "r"(a[0]), "r"(a[1]), "r"(a[2]), "r"(a[3]), "r"(b0), "r"(b1));
}
__device__ __forceinline__ void cp16(uint32_t s, const void* g) {
    asm volatile("cp.async.cg.shared.global [%0], [%1], 16;" :: "r"(s), "l"(g));
}
__device__ __forceinline__ void cp_commit() {
    asm volatile("cp.async.commit_group;" ::: "memory");
}
__device__ __forceinline__ void cp_wait0() {
    asm volatile("cp.async.wait_group 0;" ::: "memory");
}
__device__ __forceinline__ uint32_t fkey(float v) {
    uint32_t b = __float_as_uint(v);
    return (b & 0x80000000u) ? ~b : (b | 0x80000000u);
}

// ---------------- prep: codebook norms + packed fp16 hi tiles + cnp ----------------
// grid 128: blk = tile*8 + sub. sub owns nt = sub*2 + {0,1} (16 codes) + 16 cnorm rows.
__global__ void __launch_bounds__(256) vq_prep(const float* __restrict__ cb) {
    __shared__ float scn[16];
    int blk = blockIdx.x;
    int tile = blk >> 3;
    int sub = blk & 7;
    int tid = threadIdx.x;
    int lane = tid & 31;
    int grp  = tid >> 5;                  // 0..7

    if (tid < 16) {
        int k = tile * 128 + sub * 16 + tid;
        const float* r = cb + (size_t)k * DIM;
        float s = 0.f;
#pragma unroll
        for (int c4 = 0; c4 < DIM / 4; ++c4) {
            float4 v = *(const float4*)(r + c4 * 4);
            s += v.x * v.x + v.y * v.y + v.z * v.z + v.w * v.w;
        }
        g_cnorm[k] = s;
        scn[tid] = s;
    }
    __syncthreads();
    if (tid < 16) {
        // cnp slot tid: tig = tid>>2, r = tid&3
        int tig = tid >> 2, r = tid & 3;
        int local = (r >> 1) * 8 + tig * 2 + (r & 1);   // code within sub's 16
        g_cnp[tile * 128 + sub * 16 + tid] = -0.5f * scn[local];
    }

    uint32_t* dsth = g_cbf + (size_t)tile * 4096;
    int nt = sub * 2 + (grp >> 2);        // 0..15
    int kk = grp & 3;                     // 0..3
    int code = tile * 128 + nt * 8 + (lane >> 2);
    int k0 = kk * 16 + (lane & 3) * 2;
    const float* row = cb + (size_t)code * DIM;
    uint32_t b0 = packh2(row[k0], row[k0 + 1]);
    uint32_t b1 = packh2(row[k0 + 8], row[k0 + 9]);
    int region = (kk >> 1) * 2048;        // kk0/1 -> region0, kk2/3 -> region1
    int kslot = kk & 1;
    dsth[region + nt * 128 + lane * 4 + kslot * 2 + 0] = b0;
    dsth[region + nt * 128 + lane * 4 + kslot * 2 + 1] = b1;
}

// ---------------- main kernel (finalize folded in) ----------------
__global__ void __launch_bounds__(NTHREADS, 2)
vq_main(const float* __restrict__ lat, const float* __restrict__ tgt,
        const float* __restrict__ cb, const float* __restrict__ dw,
        const float* __restrict__ db, float* __restrict__ out, int out_size) {
    extern __shared__ char sm[];
    float* As = (float*)(sm + A_OFF);
    const uint32_t smem_base = smem_u32(sm);
    uint32_t* scnt = (uint32_t*)(sm + CNT_OFF);
    unsigned long long* tokmin = (unsigned long long*)(sm + TOKMIN_OFF);
    const int tid = threadIdx.x;
    const int lane = tid & 31;
    const int w = tid >> 5;              // 0..7
    const int gid = lane >> 2;           // 0..7  token-row group
    const int tig = lane & 3;            // 0..3  col group
    const int blk = blockIdx.x;
    const int n = blk >> 3;              // image (8 blocks per image)
    const int hw0 = (blk & 7) * TOK_TILE;
    uint32_t* wl = (uint32_t*)(sm + LIST_OFF) + w * WLIST;

    if (tid < 192) ((float*)(sm + DW_OFF))[tid] = dw[tid];
    if (tid < 3)   ((float*)(sm + DB_OFF))[tid] = db[tid];
    if (tid < NWARPS) scnt[tid] = 0u;
    if (tid < TOK_TILE) tokmin[tid] = ~0ull;

    // ---- stage A (fp32) [k][token]: 64 k x 128 tokens ----
    const float* latbase = lat + (size_t)n * DIM * HW + hw0;
    {
        int tl = tid & 31;               // token-float4 index
        int cgrp = tid >> 5;             // 0..7
#pragma unroll
        for (int p = 0; p < 8; ++p) {
            int c = p * 8 + cgrp;
            float4 v = *(const float4*)(latbase + (size_t)c * HW + tl * 4);
            *(float4*)&As[c * A_STRIDE + tl * 4] = v;
        }
    }

    // ---- preload B tile 0 + cnp tile 0 ----
    {
        const float4* src = (const float4*)(g_cbf);
        uint32_t dst = smem_base + B_OFF;
#pragma unroll 4
        for (int idx = tid; idx < 1024; idx += NTHREADS)
            cp16(dst + (uint32_t)idx * 16u, src + idx);
        if (tid < 32)
            cp16(smem_base + CN_OFF + (uint32_t)tid * 16u,
                 ((const float4*)g_cnp) + tid);
        cp_commit();
    }
    cp_wait0();
    __syncthreads();

    // ---- resident A hi fragments (warp = 16 tokens x 128 codes) ----
    uint32_t ah[4][4];
    const int t0 = w * 16 + gid;
#pragma unroll
    for (int kk = 0; kk < 4; ++kk) {
        int k0 = kk * 16 + tig * 2;
        ah[kk][0] = packh2(As[(k0 + 0) * A_STRIDE + t0],     As[(k0 + 1) * A_STRIDE + t0]);
        ah[kk][1] = packh2(As[(k0 + 0) * A_STRIDE + t0 + 8], As[(k0 + 1) * A_STRIDE + t0 + 8]);
        ah[kk][2] = packh2(As[(k0 + 8) * A_STRIDE + t0],     As[(k0 + 9) * A_STRIDE + t0]);
        ah[kk][3] = packh2(As[(k0 + 8) * A_STRIDE + t0 + 8], As[(k0 + 9) * A_STRIDE + t0 + 8]);
    }

    // running MAX of d = -0.5*v per token row
    float maxd0 = -3.4e38f, maxd1 = -3.4e38f;

    // 17 iterations: tiles 0..15, then tile 0 again (appends enabled from i=1)
    for (int i = 0; i <= NTILES; ++i) {
        int cur = i & 1;
        if (i < NTILES) {
            int nxt = (i + 1 == NTILES) ? 0 : i + 1;
            const float4* src = (const float4*)(g_cbf + (size_t)nxt * 4096);
            uint32_t dst = smem_base + B_OFF + (uint32_t)(cur ^ 1) * B_BUF;
#pragma unroll 4
            for (int idx = tid; idx < 1024; idx += NTHREADS)
                cp16(dst + (uint32_t)idx * 16u, src + idx);
            if (tid < 32)
                cp16(smem_base + CN_OFF + (uint32_t)(cur ^ 1) * 512u + (uint32_t)tid * 16u,
                     ((const float4*)(g_cnp + nxt * 128)) + tid);
            cp_commit();
        }

        const char* smB = sm + B_OFF + (uint32_t)cur * B_BUF;
        const float4* cns4 = (const float4*)(sm + CN_OFF + (uint32_t)cur * 512u);
        const int ti = (i == NTILES) ? 0 : i;
        const int cbase = ti * 128;
        const bool appending = (i > 0);
        const uint4* bp0 = (const uint4*)smB;             // region0: [nt][lane]
        const uint4* bp1 = (const uint4*)(smB + 8192u);   // region1: [nt][lane]

#pragma unroll
        for (int ntp = 0; ntp < 8; ++ntp) {
            int nt0 = ntp * 2;
            uint4 p0 = bp0[nt0 * 32 + lane];          // nt0 kk0,kk1
            uint4 p1 = bp1[nt0 * 32 + lane];          // nt0 kk2,kk3
            uint4 p2 = bp0[(nt0 + 1) * 32 + lane];    // nt1 kk0,kk1
            uint4 p3 = bp1[(nt0 + 1) * 32 + lane];    // nt1 kk2,kk3
            float4 cn4 = cns4[ntp * 4 + tig];         // packed -0.5*cn

            // two independent depth-4 chains, accum init = -0.5*cn -> d = -0.5*v
            float dA[4] = {cn4.x, cn4.y, cn4.x, cn4.y};   // nt0
            float dB[4] = {cn4.z, cn4.w, cn4.z, cn4.w};   // nt1
            mma_f16(dA, ah[0], p0.x, p0.y);
            mma_f16(dB, ah[0], p2.x, p2.y);
            mma_f16(dA, ah[1], p0.z, p0.w);
            mma_f16(dB, ah[1], p2.z, p2.w);
            mma_f16(dA, ah[2], p1.x, p1.y);
            mma_f16(dB, ah[2], p3.x, p3.y);
            mma_f16(dA, ah[3], p1.z, p1.w);
            mma_f16(dB, ah[3], p3.z, p3.w);

            float r0 = fmaxf(fmaxf(dA[0], dA[1]), fmaxf(dB[0], dB[1]));  // token t0
            float r1 = fmaxf(fmaxf(dA[2], dA[3]), fmaxf(dB[2], dB[3]));  // token t0+8
            bool pass = (r0 > maxd0 - HMARG) | (r1 > maxd1 - HMARG);
            if (appending) {
                if (__any_sync(0xFFFFFFFFu, pass)) {
                    float lim0 = maxd0 - HMARG, lim1 = maxd1 - HMARG;
                    int cA = cbase + nt0 * 8 + tig * 2;
                    int cB = cA + 8;
                    if (dA[0] > lim0) { uint32_t p = atomicAdd(&scnt[w], 1u); if (p < WLIST) wl[p] = ((uint32_t)t0 << 11) | (uint32_t)cA; }
                    if (dA[1] > lim0) { uint32_t p = atomicAdd(&scnt[w], 1u); if (p < WLIST) wl[p] = ((uint32_t)t0 << 11) | (uint32_t)(cA + 1); }
                    if (dA[2] > lim1) { uint32_t p = atomicAdd(&scnt[w], 1u); if (p < WLIST) wl[p] = ((uint32_t)(t0 + 8) << 11) | (uint32_t)cA; }
                    if (dA[3] > lim1) { uint32_t p = atomicAdd(&scnt[w], 1u); if (p < WLIST) wl[p] = ((uint32_t)(t0 + 8) << 11) | (uint32_t)(cA + 1); }
                    if (dB[0] > lim0) { uint32_t p = atomicAdd(&scnt[w], 1u); if (p < WLIST) wl[p] = ((uint32_t)t0 << 11) | (uint32_t)cB; }
                    if (dB[1] > lim0) { uint32_t p = atomicAdd(&scnt[w], 1u); if (p < WLIST) wl[p] = ((uint32_t)t0 << 11) | (uint32_t)(cB + 1); }
                    if (dB[2] > lim1) { uint32_t p = atomicAdd(&scnt[w], 1u); if (p < WLIST) wl[p] = ((uint32_t)(t0 + 8) << 11) | (uint32_t)cB; }
                    if (dB[3] > lim1) { uint32_t p = atomicAdd(&scnt[w], 1u); if (p < WLIST) wl[p] = ((uint32_t)(t0 + 8) << 11) | (uint32_t)(cB + 1); }
                }
            }
            maxd0 = fmaxf(maxd0, r0);
            maxd1 = fmaxf(maxd1, r1);
        }
        // combine running max across the 4 col-threads of each token row
        maxd0 = fmaxf(maxd0, __shfl_xor_sync(0xFFFFFFFFu, maxd0, 1));
        maxd0 = fmaxf(maxd0, __shfl_xor_sync(0xFFFFFFFFu, maxd0, 2));
        maxd1 = fmaxf(maxd1, __shfl_xor_sync(0xFFFFFFFFu, maxd1, 1));
        maxd1 = fmaxf(maxd1, __shfl_xor_sync(0xFFFFFFFFu, maxd1, 2));

        cp_wait0();
        __syncthreads();
    }

    // ---- exact fp32 refinement (each warp refines its own list) ----
    {
        uint32_t mycnt = scnt[w];
        if (mycnt > WLIST) mycnt = WLIST;
        for (uint32_t idx = lane; idx < mycnt; idx += 32) {
            uint32_t e = wl[idx];
            int t = (int)(e >> 11);
            int c = (int)(e & 2047u);
            const float4* er = (const float4*)(cb + (size_t)c * DIM);
            float dot = 0.f;
#pragma unroll
            for (int k4 = 0; k4 < 16; ++k4) {
                float4 ev = er[k4];
                dot += ev.x * As[(k4 * 4 + 0) * A_STRIDE + t]
                     + ev.y * As[(k4 * 4 + 1) * A_STRIDE + t]
                     + ev.z * As[(k4 * 4 + 2) * A_STRIDE + t]
                     + ev.w * As[(k4 * 4 + 3) * A_STRIDE + t];
            }
            float val = g_cnorm[c] - 2.0f * dot;
            unsigned long long pk = ((unsigned long long)fkey(val) << 32) | (unsigned)c;
            atomicMin(&tokmin[t], pk);
        }
    }
    __syncthreads();

    // ---- exact fp32 epilogue ----
    float my_vq = 0.f, my_rc = 0.f;
    if (tid < TOK_TILE) {
        int bi = (int)(tokmin[tid] & 0xFFFFFFFFu);
        const float* q = cb + (size_t)bi * DIM;
        const float* dws = (const float*)(sm + DW_OFF);
        const float* dbs = (const float*)(sm + DB_OFF);
        float y0 = dbs[0], y1 = dbs[1], y2 = dbs[2];
        float vq = 0.f;
#pragma unroll
        for (int c4 = 0; c4 < DIM / 4; ++c4) {
            float4 qv = *(const float4*)(q + c4 * 4);
            float qa[4] = {qv.x, qv.y, qv.z, qv.w};
#pragma unroll
            for (int r = 0; r < 4; ++r) {
                int c = c4 * 4 + r;
                float xc = As[c * A_STRIDE + tid];
                float dd = xc - qa[r];
                vq += dd * dd;
                y0 += dws[c] * qa[r];
                y1 += dws[DIM + c] * qa[r];
                y2 += dws[2 * DIM + c] * qa[r];
            }
        }
        const float* tg = tgt + (size_t)n * 3 * HW + hw0 + tid;
        float e0 = y0 - tg[0];
        float e1 = y1 - tg[HW];
        float e2 = y2 - tg[2 * HW];
        my_vq = vq;
        my_rc = e0 * e0 + e1 * e1 + e2 * e2;
    }
    __syncthreads();
    float* sv = (float*)(sm + RED_OFF);
    float* sr = sv + NTHREADS;
    sv[tid] = my_vq;
    sr[tid] = my_rc;
    __syncthreads();
    for (int s = NTHREADS / 2; s > 0; s >>= 1) {
        if (tid < s) { sv[tid] += sv[tid + s]; sr[tid] += sr[tid + s]; }
        __syncthreads();
    }
    if (tid == 0) {
        g_partial[blk] = sv[0];
        g_partial[NBLOCKS + blk] = sr[0];
    }

    // ---- last-block finalize (deterministic) ----
    __shared__ bool s_last;
    __threadfence();
    if (tid == 0) {
        unsigned v = atomicAdd(&g_done, 1u);
        s_last = (v == NBLOCKS - 1);
    }
    __syncthreads();
    if (s_last) {
        float v = g_partial[tid];
        float r = g_partial[NBLOCKS + tid];
        __syncthreads();
        sv[tid] = v;
        sr[tid] = r;
        __syncthreads();
        for (int s = NTHREADS / 2; s > 0; s >>= 1) {
            if (tid < s) { sv[tid] += sv[tid + s]; sr[tid] += sr[tid + s]; }
            __syncthreads();
        }
        for (int idx = tid; idx < out_size; idx += NTHREADS)
            if (idx >= 3) out[idx] = 0.f;
        if (tid == 0) {
            float vq_loss = 2.0f * sv[0] / (float)(NB * DIM * HW);
            float recon = sr[0] / (float)(NB * 3 * HW);
            if (out_size > 0) out[0] = vq_loss + recon;
            if (out_size > 1) out[1] = vq_loss;
            if (out_size > 2) out[2] = recon;
            g_done = 0;   // reset for next launch/replay
        }
    }
}

extern "C" void kernel_launch(void* const* d_in, const int* in_sizes, int n_in,
                              void* d_out, int out_size) {
    const float* lat = (const float*)d_in[0];
    const float* tgt = (const float*)d_in[1];
    const float* cb  = (const float*)d_in[2];
    const float* dw  = (const float*)d_in[3];
    const float* db  = (const float*)d_in[4];
    float* out = (float*)d_out;

    vq_prep<<<128, 256>>>(cb);

    cudaFuncSetAttribute(vq_main, cudaFuncAttributeMaxDynamicSharedMemorySize, SMEM_TOTAL);
    vq_main<<<NBLOCKS, NTHREADS, SMEM_TOTAL>>>(lat, tgt, cb, dw, db, out, out_size);
}

// round 16
// speedup vs baseline: 1.8642x; 1.0954x over previous
#include <cuda_runtime.h>
#include <cuda_fp16.h>
#include <cstdint>

// ---------------- problem constants ----------------
#define NB      32
#define DIM     64
#define HW      1024
#define KCODES  2048
#define TOK_TILE 128
#define NBLOCKS  256          // TOKENS / TOK_TILE
#define NTHREADS 256
#define NWARPS   8
#define NTILES   16           // KCODES / 128
#define WLIST    512          // per-warp candidate capacity

// int8 screening constants: s = 5.5/127 global scale
#define QINV     23.0909090909f        // 127/5.5
#define INV2S2   266.628099f           // 1/(2*s*s)
#define M_INT    480                   // margin = 1.8 (v-space) / (2 s^2)

// ---------------- dynamic smem layout (bytes) ----------------
#define A_STRIDE 132
#define A_OFF    0u                       // fp32 A [64][132]  (33792 B)
#define B_OFF    33792u                   // 2 buffers x 8KB packed s8 tiles
#define B_BUF    8192u
#define CN_OFF   50176u                   // 2 x 128 ints (packed -cn/(2s^2))
#define DW_OFF   51200u                   // 192 floats
#define DB_OFF   51968u                   // 4 floats
#define CNT_OFF  51984u                   // 8 u32 per-warp counters (+pad)
#define LIST_OFF 52032u                   // 8 x WLIST u32 (16384 B)
#define TOKMIN_OFF 68416u                 // 128 u64
#define RED_OFF  69440u                   // 2 x 256 floats
#define SMEM_TOTAL 71488u

__device__ float g_cnorm[KCODES];         // exact ||e||^2 (refine path)
// packed int accumulator inits: per tile 128 ints, [ntp 8][tig 4] int4 =
//   { c(nt0,tig*2), c(nt0,tig*2+1), c(nt1,tig*2), c(nt1,tig*2+1) }
__device__ int g_cni[NTILES * 128];
__device__ float g_partial[2 * NBLOCKS];
__device__ unsigned int g_done = 0;
// packed s8 codebook: per tile 2048 u32 = [nt 16][lane 32] uint4 =
//   { chunk0 b0, chunk0 b1, chunk1 b0, chunk1 b1 }  (m16n8k32 B frags, k chunks of 32)
__device__ uint32_t g_cbq[NTILES * 2048];

// ---------------- helpers ----------------
__device__ __forceinline__ uint32_t smem_u32(const void* p) {
    uint32_t a;
    asm("{ .reg .u64 t; cvta.to.shared.u64 t, %1; cvt.u32.u64 %0, t; }" : "=r"(a) : "l"(p));
    return a;
}
__device__ __forceinline__ int q8(float x) {
    int q = __float2int_rn(x * QINV);
    return max(-127, min(127, q));
}
__device__ __forceinline__ uint32_t pack4(float a, float b, float c, float d) {
    return (uint32_t)(q8(a) & 255) | ((uint32_t)(q8(b) & 255) << 8)
         | ((uint32_t)(q8(c) & 255) << 16) | ((uint32_t)(q8(d) & 255) << 24);
}
__device__ __forceinline__ void mma_s8(int* d, const uint32_t* a,
                                       uint32_t b0, uint32_t b1) {
    asm volatile(
        "mma.sync.aligned.m16n8k32.row.col.s32.s8.s8.s32 "
        "{%0,%1,%2,%3}, {%4,%5,%6,%7}, {%8,%9}, {%0,%1,%2,%3};"
        : "+r"(d[0]), "+r"(d[1]), "+r"(d[2]), "+r"(d[3])
        : "r"(a[0]), "r"(a[1]), "r"(a[2]), "r"(a[3]), "r"(b0), "r"(b1));
}
__device__ __forceinline__ void cp16(uint32_t s, const void* g) {
    asm volatile("cp.async.cg.shared.global [%0], [%1], 16;" :: "r"(s), "l"(g));
}
__device__ __forceinline__ void cp_commit() {
    asm volatile("cp.async.commit_group;" ::: "memory");
}
__device__ __forceinline__ void cp_wait0() {
    asm volatile("cp.async.wait_group 0;" ::: "memory");
}
__device__ __forceinline__ uint32_t fkey(float v) {
    uint32_t b = __float_as_uint(v);
    return (b & 0x80000000u) ? ~b : (b | 0x80000000u);
}

// ---------------- prep: codebook norms + s8 fragment pack + int inits ----------------
// grid 128: blk = tile*8 + sub. sub owns nt = sub*2 + {0,1} + 16 cnorm rows.
__global__ void __launch_bounds__(256) vq_prep(const float* __restrict__ cb) {
    __shared__ float scn[16];
    int blk = blockIdx.x;
    int tile = blk >> 3;
    int sub = blk & 7;
    int tid = threadIdx.x;

    if (tid < 16) {
        int k = tile * 128 + sub * 16 + tid;
        const float* r = cb + (size_t)k * DIM;
        float s = 0.f;
#pragma unroll
        for (int c4 = 0; c4 < DIM / 4; ++c4) {
            float4 v = *(const float4*)(r + c4 * 4);
            s += v.x * v.x + v.y * v.y + v.z * v.z + v.w * v.w;
        }
        g_cnorm[k] = s;
        scn[tid] = s;
    }
    __syncthreads();
    if (tid < 16) {
        int tig = tid >> 2, r = tid & 3;
        int local = (r >> 1) * 8 + tig * 2 + (r & 1);   // code within sub's 16
        g_cni[tile * 128 + sub * 16 + tid] = __float2int_rn(-scn[local] * INV2S2);
    }

    // s8 B fragments: threads 0..63 each pack one (nt, lane) uint4
    if (tid < 64) {
        int nt = sub * 2 + (tid >> 5);
        int lane = tid & 31;
        int code = tile * 128 + nt * 8 + (lane >> 2);
        int kb = (lane & 3) * 4;
        const float* row = cb + (size_t)code * DIM;
        uint32_t* dst = g_cbq + (size_t)tile * 2048 + nt * 128 + lane * 4;
        dst[0] = pack4(row[kb + 0],  row[kb + 1],  row[kb + 2],  row[kb + 3]);
        dst[1] = pack4(row[kb + 16], row[kb + 17], row[kb + 18], row[kb + 19]);
        dst[2] = pack4(row[kb + 32], row[kb + 33], row[kb + 34], row[kb + 35]);
        dst[3] = pack4(row[kb + 48], row[kb + 49], row[kb + 50], row[kb + 51]);
    }
}

// ---------------- main kernel (finalize folded in) ----------------
__global__ void __launch_bounds__(NTHREADS, 2)
vq_main(const float* __restrict__ lat, const float* __restrict__ tgt,
        const float* __restrict__ cb, const float* __restrict__ dw,
        const float* __restrict__ db, float* __restrict__ out, int out_size) {
    extern __shared__ char sm[];
    float* As = (float*)(sm + A_OFF);
    const uint32_t smem_base = smem_u32(sm);
    uint32_t* scnt = (uint32_t*)(sm + CNT_OFF);
    unsigned long long* tokmin = (unsigned long long*)(sm + TOKMIN_OFF);
    const int tid = threadIdx.x;
    const int lane = tid & 31;
    const int w = tid >> 5;              // 0..7
    const int gid = lane >> 2;           // 0..7  token-row group
    const int tig = lane & 3;            // 0..3  col group
    const int blk = blockIdx.x;
    const int n = blk >> 3;              // image (8 blocks per image)
    const int hw0 = (blk & 7) * TOK_TILE;
    uint32_t* wl = (uint32_t*)(sm + LIST_OFF) + w * WLIST;

    if (tid < 192) ((float*)(sm + DW_OFF))[tid] = dw[tid];
    if (tid < 3)   ((float*)(sm + DB_OFF))[tid] = db[tid];
    if (tid < NWARPS) scnt[tid] = 0u;
    if (tid < TOK_TILE) tokmin[tid] = ~0ull;

    // ---- stage A (fp32) [k][token]: 64 k x 128 tokens ----
    const float* latbase = lat + (size_t)n * DIM * HW + hw0;
    {
        int tl = tid & 31;
        int cgrp = tid >> 5;
#pragma unroll
        for (int p = 0; p < 8; ++p) {
            int c = p * 8 + cgrp;
            float4 v = *(const float4*)(latbase + (size_t)c * HW + tl * 4);
            *(float4*)&As[c * A_STRIDE + tl * 4] = v;
        }
    }

    // ---- preload B tile 0 + cni tile 0 ----
    {
        const float4* src = (const float4*)(g_cbq);
        uint32_t dst = smem_base + B_OFF;
#pragma unroll 2
        for (int idx = tid; idx < 512; idx += NTHREADS)
            cp16(dst + (uint32_t)idx * 16u, src + idx);
        if (tid < 32)
            cp16(smem_base + CN_OFF + (uint32_t)tid * 16u,
                 ((const float4*)g_cni) + tid);
        cp_commit();
    }
    cp_wait0();
    __syncthreads();

    // ---- resident A s8 fragments (warp = 16 tokens x 128 codes) ----
    uint32_t aq[2][4];
    const int t0 = w * 16 + gid;
#pragma unroll
    for (int c = 0; c < 2; ++c) {
        int kb = c * 32 + tig * 4;
        aq[c][0] = pack4(As[(kb + 0) * A_STRIDE + t0], As[(kb + 1) * A_STRIDE + t0],
                         As[(kb + 2) * A_STRIDE + t0], As[(kb + 3) * A_STRIDE + t0]);
        aq[c][1] = pack4(As[(kb + 0) * A_STRIDE + t0 + 8], As[(kb + 1) * A_STRIDE + t0 + 8],
                         As[(kb + 2) * A_STRIDE + t0 + 8], As[(kb + 3) * A_STRIDE + t0 + 8]);
        aq[c][2] = pack4(As[(kb + 16) * A_STRIDE + t0], As[(kb + 17) * A_STRIDE + t0],
                         As[(kb + 18) * A_STRIDE + t0], As[(kb + 19) * A_STRIDE + t0]);
        aq[c][3] = pack4(As[(kb + 16) * A_STRIDE + t0 + 8], As[(kb + 17) * A_STRIDE + t0 + 8],
                         As[(kb + 18) * A_STRIDE + t0 + 8], As[(kb + 19) * A_STRIDE + t0 + 8]);
    }

    // running MAX of D = dot_q - cn/(2s^2) per token row (int; bigger = closer)
    int maxd0 = -2000000000, maxd1 = -2000000000;

    // 17 iterations: tiles 0..15, then tile 0 again (appends enabled from i=1)
    for (int i = 0; i <= NTILES; ++i) {
        int cur = i & 1;
        if (i < NTILES) {
            int nxt = (i + 1 == NTILES) ? 0 : i + 1;
            const float4* src = (const float4*)(g_cbq + (size_t)nxt * 2048);
            uint32_t dst = smem_base + B_OFF + (uint32_t)(cur ^ 1) * B_BUF;
#pragma unroll 2
            for (int idx = tid; idx < 512; idx += NTHREADS)
                cp16(dst + (uint32_t)idx * 16u, src + idx);
            if (tid < 32)
                cp16(smem_base + CN_OFF + (uint32_t)(cur ^ 1) * 512u + (uint32_t)tid * 16u,
                     ((const float4*)(g_cni + nxt * 128)) + tid);
            cp_commit();
        }

        const char* smB = sm + B_OFF + (uint32_t)cur * B_BUF;
        const int4* cni4 = (const int4*)(sm + CN_OFF + (uint32_t)cur * 512u);
        const int ti = (i == NTILES) ? 0 : i;
        const int cbase = ti * 128;
        const bool appending = (i > 0);
        const uint4* bp = (const uint4*)smB;   // [nt][lane]

#pragma unroll
        for (int ntp = 0; ntp < 8; ++ntp) {
            int nt0 = ntp * 2;
            uint4 b0 = bp[nt0 * 32 + lane];          // nt0: {c0b0,c0b1,c1b0,c1b1}
            uint4 b1 = bp[(nt0 + 1) * 32 + lane];    // nt1
            int4 cn4 = cni4[ntp * 4 + tig];          // packed -cn/(2s^2)

            int dA[4] = {cn4.x, cn4.y, cn4.x, cn4.y};   // nt0
            int dB[4] = {cn4.z, cn4.w, cn4.z, cn4.w};   // nt1
            mma_s8(dA, aq[0], b0.x, b0.y);
            mma_s8(dB, aq[0], b1.x, b1.y);
            mma_s8(dA, aq[1], b0.z, b0.w);
            mma_s8(dB, aq[1], b1.z, b1.w);

            int r0 = max(max(dA[0], dA[1]), max(dB[0], dB[1]));  // token t0
            int r1 = max(max(dA[2], dA[3]), max(dB[2], dB[3]));  // token t0+8
            bool pass = (r0 > maxd0 - M_INT) | (r1 > maxd1 - M_INT);
            if (appending) {
                if (__any_sync(0xFFFFFFFFu, pass)) {
                    int lim0 = maxd0 - M_INT, lim1 = maxd1 - M_INT;
                    int cA = cbase + nt0 * 8 + tig * 2;
                    int cB = cA + 8;
                    if (dA[0] > lim0) { uint32_t p = atomicAdd(&scnt[w], 1u); if (p < WLIST) wl[p] = ((uint32_t)t0 << 11) | (uint32_t)cA; }
                    if (dA[1] > lim0) { uint32_t p = atomicAdd(&scnt[w], 1u); if (p < WLIST) wl[p] = ((uint32_t)t0 << 11) | (uint32_t)(cA + 1); }
                    if (dA[2] > lim1) { uint32_t p = atomicAdd(&scnt[w], 1u); if (p < WLIST) wl[p] = ((uint32_t)(t0 + 8) << 11) | (uint32_t)cA; }
                    if (dA[3] > lim1) { uint32_t p = atomicAdd(&scnt[w], 1u); if (p < WLIST) wl[p] = ((uint32_t)(t0 + 8) << 11) | (uint32_t)(cA + 1); }
                    if (dB[0] > lim0) { uint32_t p = atomicAdd(&scnt[w], 1u); if (p < WLIST) wl[p] = ((uint32_t)t0 << 11) | (uint32_t)cB; }
                    if (dB[1] > lim0) { uint32_t p = atomicAdd(&scnt[w], 1u); if (p < WLIST) wl[p] = ((uint32_t)t0 << 11) | (uint32_t)(cB + 1); }
                    if (dB[2] > lim1) { uint32_t p = atomicAdd(&scnt[w], 1u); if (p < WLIST) wl[p] = ((uint32_t)(t0 + 8) << 11) | (uint32_t)cB; }
                    if (dB[3] > lim1) { uint32_t p = atomicAdd(&scnt[w], 1u); if (p < WLIST) wl[p] = ((uint32_t)(t0 + 8) << 11) | (uint32_t)(cB + 1); }
                }
            }
            maxd0 = max(maxd0, r0);
            maxd1 = max(maxd1, r1);
        }
        // combine running max across the 4 col-threads of each token row
        maxd0 = max(maxd0, __shfl_xor_sync(0xFFFFFFFFu, maxd0, 1));
        maxd0 = max(maxd0, __shfl_xor_sync(0xFFFFFFFFu, maxd0, 2));
        maxd1 = max(maxd1, __shfl_xor_sync(0xFFFFFFFFu, maxd1, 1));
        maxd1 = max(maxd1, __shfl_xor_sync(0xFFFFFFFFu, maxd1, 2));

        cp_wait0();
        __syncthreads();
    }

    // ---- exact fp32 refinement (each warp refines its own list) ----
    {
        uint32_t mycnt = scnt[w];
        if (mycnt > WLIST) mycnt = WLIST;
        for (uint32_t idx = lane; idx < mycnt; idx += 32) {
            uint32_t e = wl[idx];
            int t = (int)(e >> 11);
            int c = (int)(e & 2047u);
            const float4* er = (const float4*)(cb + (size_t)c * DIM);
            float dot = 0.f;
#pragma unroll
            for (int k4 = 0; k4 < 16; ++k4) {
                float4 ev = er[k4];
                dot += ev.x * As[(k4 * 4 + 0) * A_STRIDE + t]
                     + ev.y * As[(k4 * 4 + 1) * A_STRIDE + t]
                     + ev.z * As[(k4 * 4 + 2) * A_STRIDE + t]
                     + ev.w * As[(k4 * 4 + 3) * A_STRIDE + t];
            }
            float val = g_cnorm[c] - 2.0f * dot;
            unsigned long long pk = ((unsigned long long)fkey(val) << 32) | (unsigned)c;
            atomicMin(&tokmin[t], pk);
        }
    }
    __syncthreads();

    // ---- exact fp32 epilogue ----
    float my_vq = 0.f, my_rc = 0.f;
    if (tid < TOK_TILE) {
        int bi = (int)(tokmin[tid] & 0xFFFFFFFFu);
        const float* q = cb + (size_t)bi * DIM;
        const float* dws = (const float*)(sm + DW_OFF);
        const float* dbs = (const float*)(sm + DB_OFF);
        float y0 = dbs[0], y1 = dbs[1], y2 = dbs[2];
        float vq = 0.f;
#pragma unroll
        for (int c4 = 0; c4 < DIM / 4; ++c4) {
            float4 qv = *(const float4*)(q + c4 * 4);
            float qa[4] = {qv.x, qv.y, qv.z, qv.w};
#pragma unroll
            for (int r = 0; r < 4; ++r) {
                int c = c4 * 4 + r;
                float xc = As[c * A_STRIDE + tid];
                float dd = xc - qa[r];
                vq += dd * dd;
                y0 += dws[c] * qa[r];
                y1 += dws[DIM + c] * qa[r];
                y2 += dws[2 * DIM + c] * qa[r];
            }
        }
        const float* tg = tgt + (size_t)n * 3 * HW + hw0 + tid;
        float e0 = y0 - tg[0];
        float e1 = y1 - tg[HW];
        float e2 = y2 - tg[2 * HW];
        my_vq = vq;
        my_rc = e0 * e0 + e1 * e1 + e2 * e2;
    }
    __syncthreads();
    float* sv = (float*)(sm + RED_OFF);
    float* sr = sv + NTHREADS;
    sv[tid] = my_vq;
    sr[tid] = my_rc;
    __syncthreads();
    for (int s = NTHREADS / 2; s > 0; s >>= 1) {
        if (tid < s) { sv[tid] += sv[tid + s]; sr[tid] += sr[tid + s]; }
        __syncthreads();
    }
    if (tid == 0) {
        g_partial[blk] = sv[0];
        g_partial[NBLOCKS + blk] = sr[0];
    }

    // ---- last-block finalize (deterministic) ----
    __shared__ bool s_last;
    __threadfence();
    if (tid == 0) {
        unsigned v = atomicAdd(&g_done, 1u);
        s_last = (v == NBLOCKS - 1);
    }
    __syncthreads();
    if (s_last) {
        float v = g_partial[tid];
        float r = g_partial[NBLOCKS + tid];
        __syncthreads();
        sv[tid] = v;
        sr[tid] = r;
        __syncthreads();
        for (int s = NTHREADS / 2; s > 0; s >>= 1) {
            if (tid < s) { sv[tid] += sv[tid + s]; sr[tid] += sr[tid + s]; }
            __syncthreads();
        }
        for (int idx = tid; idx < out_size; idx += NTHREADS)
            if (idx >= 3) out[idx] = 0.f;
        if (tid == 0) {
            float vq_loss = 2.0f * sv[0] / (float)(NB * DIM * HW);
            float recon = sr[0] / (float)(NB * 3 * HW);
            if (out_size > 0) out[0] = vq_loss + recon;
            if (out_size > 1) out[1] = vq_loss;
            if (out_size > 2) out[2] = recon;
            g_done = 0;   // reset for next launch/replay
        }
    }
}

extern "C" void kernel_launch(void* const* d_in, const int* in_sizes, int n_in,
                              void* d_out, int out_size) {
    const float* lat = (const float*)d_in[0];
    const float* tgt = (const float*)d_in[1];
    const float* cb  = (const float*)d_in[2];
    const float* dw  = (const float*)d_in[3];
    const float* db  = (const float*)d_in[4];
    float* out = (float*)d_out;

    vq_prep<<<128, 256>>>(cb);

    cudaFuncSetAttribute(vq_main, cudaFuncAttributeMaxDynamicSharedMemorySize, SMEM_TOTAL);
    vq_main<<<NBLOCKS, NTHREADS, SMEM_TOTAL>>>(lat, tgt, cb, dw, db, out, out_size);
}